// round 2
// baseline (speedup 1.0000x reference)
#include <cuda_runtime.h>

typedef unsigned long long ull;

#define NSEQ 2048
#define NRES 512
#define CIN  64
#define NH   8
#define NC   8

// ---------------- scratch (device globals: allocation-free) ----------------
__device__ __align__(16) float g_k[(size_t)NRES * NSEQ * NC];     // 32 MB
__device__ __align__(16) float g_v[(size_t)NRES * NSEQ * NC];     // 32 MB
__device__ __align__(16) float g_qsum[NRES * CIN];
__device__ __align__(16) float g_msum[NRES];
__device__ __align__(16) float g_o[NRES * CIN];

// ---------------- packed f32x2 helpers ----------------
__device__ __forceinline__ ull fma2(ull a, ull b, ull c) {
    ull d;
    asm("fma.rn.f32x2 %0, %1, %2, %3;" : "=l"(d) : "l"(a), "l"(b), "l"(c));
    return d;
}
__device__ __forceinline__ ull dup2(float x) {
    ull d; unsigned xi = __float_as_uint(x);
    asm("mov.b64 %0, {%1, %1};" : "=l"(d) : "r"(xi));
    return d;
}
__device__ __forceinline__ float2 unpk(ull a) {
    unsigned lo, hi;
    asm("mov.b64 {%0, %1}, %2;" : "=r"(lo), "=r"(hi) : "l"(a));
    return make_float2(__uint_as_float(lo), __uint_as_float(hi));
}

__device__ __forceinline__ float wsum(float v) {
#pragma unroll
    for (int o = 16; o; o >>= 1) v += __shfl_xor_sync(0xffffffffu, v, o);
    return v;
}
__device__ __forceinline__ float wmax(float v) {
#pragma unroll
    for (int o = 16; o; o >>= 1) v = fmaxf(v, __shfl_xor_sync(0xffffffffu, v, o));
    return v;
}

// =====================================================================
// Pass 1: per column r — layernorm, k/v projection, masked q-sum.
// One block per r, 256 threads, thread-owns-row (x register-resident).
// =====================================================================
__global__ __launch_bounds__(256) void pass1_kernel(
    const float* __restrict__ m, const float* __restrict__ mask,
    const float* __restrict__ lnw, const float* __restrict__ lnb,
    const float* __restrict__ wk, const float* __restrict__ wv)
{
    const int r = blockIdx.x;
    const int tid = threadIdx.x;
    const int lane = tid & 31, warp = tid >> 5;

    __shared__ __align__(16) float wkv_s[CIN * 16];   // [c][j] j<8:k, j>=8:v
    __shared__ float lnw_s[CIN], lnb_s[CIN];
    __shared__ float qred[8][CIN];
    __shared__ float mred[8];

    for (int i = tid; i < CIN * 16; i += 256) {
        int c = i >> 4, j = i & 15;
        wkv_s[i] = (j < 8) ? wk[c * 8 + j] : wv[c * 8 + (j - 8)];
    }
    if (tid < CIN) { lnw_s[tid] = lnw[tid]; lnb_s[tid] = lnb[tid]; }
    __syncthreads();

    float qacc[CIN];
#pragma unroll
    for (int c = 0; c < CIN; c++) qacc[c] = 0.f;
    float macc = 0.f;

    for (int it = 0; it < NSEQ / 256; it++) {
        const int n = it * 256 + tid;
        const float4* mrow = (const float4*)(m + ((size_t)n * NRES + r) * CIN);
        float x[CIN];
        float s = 0.f, sq = 0.f;
#pragma unroll
        for (int k = 0; k < 16; k++) {
            float4 v4 = mrow[k];
            x[4 * k + 0] = v4.x; x[4 * k + 1] = v4.y;
            x[4 * k + 2] = v4.z; x[4 * k + 3] = v4.w;
            s  += v4.x + v4.y + v4.z + v4.w;
            sq += v4.x * v4.x + v4.y * v4.y + v4.z * v4.z + v4.w * v4.w;
        }
        float mu = s * (1.f / CIN);
        float rs = rsqrtf(sq * (1.f / CIN) - mu * mu + 1e-5f);
#pragma unroll
        for (int c = 0; c < CIN; c++) x[c] = (x[c] - mu) * rs * lnw_s[c] + lnb_s[c];

        float mv = mask[(size_t)n * NRES + r];
        macc += mv;
#pragma unroll
        for (int c = 0; c < CIN; c++) qacc[c] += mv * x[c];

        ull a2[8];
#pragma unroll
        for (int j = 0; j < 8; j++) a2[j] = 0ull;
#pragma unroll
        for (int c = 0; c < CIN; c++) {
            ull xc = dup2(x[c]);
            const ulonglong2* wr = (const ulonglong2*)(wkv_s + c * 16);
#pragma unroll
            for (int i2 = 0; i2 < 4; i2++) {
                ulonglong2 w2 = wr[i2];
                a2[2 * i2]     = fma2(xc, w2.x, a2[2 * i2]);
                a2[2 * i2 + 1] = fma2(xc, w2.y, a2[2 * i2 + 1]);
            }
        }
        ulonglong2* kp = (ulonglong2*)(g_k + ((size_t)r * NSEQ + n) * NC);
        ulonglong2* vp = (ulonglong2*)(g_v + ((size_t)r * NSEQ + n) * NC);
        ulonglong2 t0; t0.x = a2[0]; t0.y = a2[1]; kp[0] = t0;
        ulonglong2 t1; t1.x = a2[2]; t1.y = a2[3]; kp[1] = t1;
        ulonglong2 t2; t2.x = a2[4]; t2.y = a2[5]; vp[0] = t2;
        ulonglong2 t3; t3.x = a2[6]; t3.y = a2[7]; vp[1] = t3;
    }

    // deterministic block reduction (warp shuffle -> fixed-order shared sum)
#pragma unroll
    for (int c = 0; c < CIN; c++) {
        float v = wsum(qacc[c]);
        if (lane == 0) qred[warp][c] = v;
    }
    float mt = wsum(macc);
    if (lane == 0) mred[warp] = mt;
    __syncthreads();
    if (tid < CIN) {
        float s2 = 0.f;
#pragma unroll
        for (int w = 0; w < 8; w++) s2 += qred[w][tid];
        g_qsum[r * CIN + tid] = s2;
    }
    if (tid == 0) {
        float s2 = 0.f;
#pragma unroll
        for (int w = 0; w < 8; w++) s2 += mred[w];
        g_msum[r] = s2;
    }
}

// =====================================================================
// Pass 2: per column r — q projection, logits, softmax, o accumulation.
// =====================================================================
__global__ __launch_bounds__(256) void pass2_kernel(
    const float* __restrict__ mask, const float* __restrict__ wq)
{
    const int r = blockIdx.x;
    const int tid = threadIdx.x;
    const int lane = tid & 31, warp = tid >> 5;

    __shared__ float qpre[CIN];
    __shared__ float qh[CIN];
    __shared__ float redm[8][NH];
    __shared__ float reds[8][NH];
    __shared__ float hmax_s[NH], hsum_s[NH];
    __shared__ float ored[8][CIN];

    if (tid < CIN) qpre[tid] = g_qsum[r * CIN + tid] / (g_msum[r] + 1e-10f);
    __syncthreads();
    if (tid < CIN) {
        float a = 0.f;
#pragma unroll
        for (int c = 0; c < CIN; c++) a += qpre[c] * wq[c * CIN + tid];
        qh[tid] = a * 0.3535533905932738f;   // C^-0.5
    }
    __syncthreads();

    float l[8][NH];
    float hmax[NH];
#pragma unroll
    for (int h = 0; h < NH; h++) hmax[h] = -3.4e38f;

#pragma unroll
    for (int i = 0; i < 8; i++) {
        int n = i * 256 + tid;
        const float4* kp = (const float4*)(g_k + ((size_t)r * NSEQ + n) * NC);
        float4 k0 = kp[0], k1 = kp[1];
        float bias = (mask[(size_t)n * NRES + r] - 1.f) * 1000000000.0f;
#pragma unroll
        for (int h = 0; h < NH; h++) {
            const float* q = qh + h * NC;
            float a = q[0] * k0.x + q[1] * k0.y + q[2] * k0.z + q[3] * k0.w
                    + q[4] * k1.x + q[5] * k1.y + q[6] * k1.z + q[7] * k1.w;
            a += bias;
            l[i][h] = a;
            hmax[h] = fmaxf(hmax[h], a);
        }
    }
#pragma unroll
    for (int h = 0; h < NH; h++) {
        float v = wmax(hmax[h]);
        if (lane == 0) redm[warp][h] = v;
    }
    __syncthreads();
    if (tid < NH) {
        float v = -3.4e38f;
#pragma unroll
        for (int w = 0; w < 8; w++) v = fmaxf(v, redm[w][tid]);
        hmax_s[tid] = v;
    }
    __syncthreads();

    float hsum[NH];
#pragma unroll
    for (int h = 0; h < NH; h++) hsum[h] = 0.f;
    float oacc[CIN];
#pragma unroll
    for (int j = 0; j < CIN; j++) oacc[j] = 0.f;

#pragma unroll
    for (int i = 0; i < 8; i++) {
        int n = i * 256 + tid;
        const float4* vp = (const float4*)(g_v + ((size_t)r * NSEQ + n) * NC);
        float4 v0 = vp[0], v1 = vp[1];
#pragma unroll
        for (int h = 0; h < NH; h++) {
            float p = __expf(l[i][h] - hmax_s[h]);
            hsum[h] += p;
            oacc[h * 8 + 0] += p * v0.x; oacc[h * 8 + 1] += p * v0.y;
            oacc[h * 8 + 2] += p * v0.z; oacc[h * 8 + 3] += p * v0.w;
            oacc[h * 8 + 4] += p * v1.x; oacc[h * 8 + 5] += p * v1.y;
            oacc[h * 8 + 6] += p * v1.z; oacc[h * 8 + 7] += p * v1.w;
        }
    }
#pragma unroll
    for (int h = 0; h < NH; h++) {
        float v = wsum(hsum[h]);
        if (lane == 0) reds[warp][h] = v;
    }
#pragma unroll
    for (int j = 0; j < CIN; j++) {
        float v = wsum(oacc[j]);
        if (lane == 0) ored[warp][j] = v;
    }
    __syncthreads();
    if (tid < NH) {
        float v = 0.f;
#pragma unroll
        for (int w = 0; w < 8; w++) v += reds[w][tid];
        hsum_s[tid] = v;
    }
    __syncthreads();
    if (tid < CIN) {
        float s2 = 0.f;
#pragma unroll
        for (int w = 0; w < 8; w++) s2 += ored[w][tid];
        g_o[r * CIN + tid] = s2 / hsum_s[tid >> 3];
    }
}

// =====================================================================
// Pass 3 (hot): per (n,r) — layernorm, g = sigmoid(x@Wg + bg),
// out = (o ⊙ g) @ Wo + bo. Thread-owns-row, all FMA2, weights via
// LDS.128 all-lane broadcasts.
// =====================================================================
__global__ __launch_bounds__(256) void pass3_kernel(
    const float* __restrict__ m,
    const float* __restrict__ lnw, const float* __restrict__ lnb,
    const float* __restrict__ wg, const float* __restrict__ bg,
    const float* __restrict__ wo, const float* __restrict__ bo,
    float* __restrict__ out)
{
    const int r = blockIdx.x;
    const int tid = threadIdx.x;
    const int n = blockIdx.y * 256 + tid;

    __shared__ __align__(16) float wg_s[CIN * CIN];
    __shared__ __align__(16) float wo_s[CIN * CIN];
    __shared__ __align__(16) float lnw_s[CIN], lnb_s[CIN];
    __shared__ __align__(16) float o_s[CIN];
    __shared__ __align__(16) float bg_s[CIN];
    __shared__ __align__(16) float bo_s[CIN];

    for (int i = tid; i < CIN * CIN; i += 256) { wg_s[i] = wg[i]; wo_s[i] = wo[i]; }
    if (tid < CIN) {
        lnw_s[tid] = lnw[tid]; lnb_s[tid] = lnb[tid];
        o_s[tid] = g_o[r * CIN + tid];
        bg_s[tid] = bg[tid]; bo_s[tid] = bo[tid];
    }
    __syncthreads();

    // ---- layernorm row ----
    const float4* mrow = (const float4*)(m + ((size_t)n * NRES + r) * CIN);
    float x[CIN];
    {
        float s = 0.f, sq = 0.f;
#pragma unroll
        for (int k = 0; k < 16; k++) {
            float4 v4 = mrow[k];
            x[4 * k + 0] = v4.x; x[4 * k + 1] = v4.y;
            x[4 * k + 2] = v4.z; x[4 * k + 3] = v4.w;
            s  += v4.x + v4.y + v4.z + v4.w;
            sq += v4.x * v4.x + v4.y * v4.y + v4.z * v4.z + v4.w * v4.w;
        }
        float mu = s * (1.f / CIN);
        float rs = rsqrtf(sq * (1.f / CIN) - mu * mu + 1e-5f);
#pragma unroll
        for (int c = 0; c < CIN; c++) x[c] = (x[c] - mu) * rs * lnw_s[c] + lnb_s[c];
    }

    // ---- GEMM 1: gpre[j] = sum_c x[c] * wg[c][j]  (acc in f32x2 pairs) ----
    ull ga[32];
    {
        const ull* bgp = (const ull*)bg_s;
#pragma unroll
        for (int p = 0; p < 32; p++) ga[p] = bgp[p];   // init with bias
#pragma unroll
        for (int c = 0; c < CIN; c++) {
            ull xc = dup2(x[c]);
            const ulonglong2* wr = (const ulonglong2*)(wg_s + c * CIN);
#pragma unroll
            for (int i2 = 0; i2 < 16; i2++) {
                ulonglong2 w2 = wr[i2];
                ga[2 * i2]     = fma2(xc, w2.x, ga[2 * i2]);
                ga[2 * i2 + 1] = fma2(xc, w2.y, ga[2 * i2 + 1]);
            }
        }
    }

    // ---- gate + GEMM 2: out[c] = sum_j (o[j]*sigmoid(gpre[j])) * wo[j][c] ----
    ull oa[32];
    {
        const ull* bop = (const ull*)bo_s;
#pragma unroll
        for (int p = 0; p < 32; p++) oa[p] = bop[p];   // init with bias
#pragma unroll
        for (int p = 0; p < 32; p++) {
            float2 t = unpk(ga[p]);
            int j0 = 2 * p, j1 = 2 * p + 1;
            float y0 = o_s[j0] / (1.f + __expf(-t.x));
            float y1 = o_s[j1] / (1.f + __expf(-t.y));
            ull y0d = dup2(y0), y1d = dup2(y1);
            const ulonglong2* wr0 = (const ulonglong2*)(wo_s + j0 * CIN);
            const ulonglong2* wr1 = (const ulonglong2*)(wo_s + j1 * CIN);
#pragma unroll
            for (int i2 = 0; i2 < 16; i2++) {
                ulonglong2 w20 = wr0[i2];
                oa[2 * i2]     = fma2(y0d, w20.x, oa[2 * i2]);
                oa[2 * i2 + 1] = fma2(y0d, w20.y, oa[2 * i2 + 1]);
            }
#pragma unroll
            for (int i2 = 0; i2 < 16; i2++) {
                ulonglong2 w21 = wr1[i2];
                oa[2 * i2]     = fma2(y1d, w21.x, oa[2 * i2]);
                oa[2 * i2 + 1] = fma2(y1d, w21.y, oa[2 * i2 + 1]);
            }
        }
    }

    // ---- store out[n][r][:] ----
    ulonglong2* op = (ulonglong2*)(out + ((size_t)n * NRES + r) * CIN);
#pragma unroll
    for (int i2 = 0; i2 < 16; i2++) {
        ulonglong2 t; t.x = oa[2 * i2]; t.y = oa[2 * i2 + 1];
        op[i2] = t;
    }
}

extern "C" void kernel_launch(void* const* d_in, const int* in_sizes, int n_in,
                              void* d_out, int out_size) {
    const float* m    = (const float*)d_in[0];
    const float* mask = (const float*)d_in[1];
    const float* lnw  = (const float*)d_in[2];
    const float* lnb  = (const float*)d_in[3];
    const float* wq   = (const float*)d_in[4];
    const float* wk   = (const float*)d_in[5];
    const float* wv   = (const float*)d_in[6];
    const float* wg   = (const float*)d_in[7];
    const float* bg   = (const float*)d_in[8];
    const float* wo   = (const float*)d_in[9];
    const float* bo   = (const float*)d_in[10];
    float* out = (float*)d_out;

    pass1_kernel<<<NRES, 256>>>(m, mask, lnw, lnb, wk, wv);
    pass2_kernel<<<NRES, 256>>>(mask, wq);
    pass3_kernel<<<dim3(NRES, NSEQ / 256), 256>>>(m, lnw, lnb, wg, bg, wo, bo, out);
}

// round 3
// speedup vs baseline: 1.2803x; 1.2803x over previous
#include <cuda_runtime.h>

typedef unsigned long long ull;

#define NSEQ 2048
#define NRES 512
#define CIN  64
#define NH   8
#define NC   8

// ---------------- scratch (device globals: allocation-free) ----------------
__device__ __align__(16) float g_k[(size_t)NRES * NSEQ * NC];     // 32 MB
__device__ __align__(16) float g_v[(size_t)NRES * NSEQ * NC];     // 32 MB
__device__ __align__(16) float g_qsum[NRES * CIN];
__device__ __align__(16) float g_msum[NRES];
__device__ __align__(16) float g_o[NRES * CIN];

// ---------------- packed f32x2 helpers ----------------
__device__ __forceinline__ ull fma2(ull a, ull b, ull c) {
    ull d;
    asm("fma.rn.f32x2 %0, %1, %2, %3;" : "=l"(d) : "l"(a), "l"(b), "l"(c));
    return d;
}
__device__ __forceinline__ ull add2(ull a, ull b) {
    ull d;
    asm("add.rn.f32x2 %0, %1, %2;" : "=l"(d) : "l"(a), "l"(b));
    return d;
}
__device__ __forceinline__ ull dup2(float x) {
    ull d; unsigned xi = __float_as_uint(x);
    asm("mov.b64 %0, {%1, %1};" : "=l"(d) : "r"(xi));
    return d;
}
__device__ __forceinline__ float2 unpk(ull a) {
    unsigned lo, hi;
    asm("mov.b64 {%0, %1}, %2;" : "=r"(lo), "=r"(hi) : "l"(a));
    return make_float2(__uint_as_float(lo), __uint_as_float(hi));
}
__device__ __forceinline__ ull shfl64x(ull v, int m) {
    return __shfl_xor_sync(0xffffffffu, v, m);
}
__device__ __forceinline__ float wsum(float v) {
#pragma unroll
    for (int o = 16; o; o >>= 1) v += __shfl_xor_sync(0xffffffffu, v, o);
    return v;
}

// =====================================================================
// Pass 1: per column r — layernorm, k/v projection, masked q-sum.
// 256 threads = 128 row-slots x 2 lanes; each lane owns 32 channels.
// =====================================================================
__global__ void __launch_bounds__(256, 2) pass1_kernel(
    const float* __restrict__ m, const float* __restrict__ mask,
    const float* __restrict__ lnw, const float* __restrict__ lnb,
    const float* __restrict__ wk, const float* __restrict__ wv)
{
    const int r = blockIdx.x;
    const int tid = threadIdx.x;
    const int lane = tid & 31, warp = tid >> 5;
    const int slot = tid >> 1, parity = tid & 1;
    const int cbase = parity * 32;

    __shared__ __align__(16) float wkv_s[CIN * 16];   // [c][j] j<8:k else v
    __shared__ float lnw_s[CIN], lnb_s[CIN];
    __shared__ float qred[8][CIN];
    __shared__ float mred[8];

    for (int i = tid; i < CIN * 16; i += 256) {
        int c = i >> 4, j = i & 15;
        wkv_s[i] = (j < 8) ? wk[c * 8 + j] : wv[c * 8 + (j - 8)];
    }
    if (tid < CIN) { lnw_s[tid] = lnw[tid]; lnb_s[tid] = lnb[tid]; }
    __syncthreads();

    float qacc[32];
#pragma unroll
    for (int c = 0; c < 32; c++) qacc[c] = 0.f;
    float macc = 0.f;

    for (int it = 0; it < NSEQ / 128; it++) {
        const int n = it * 128 + slot;
        const float4* mrow = (const float4*)(m + ((size_t)n * NRES + r) * CIN) + parity * 8;
        float x[32];
        float s = 0.f, sq = 0.f;
#pragma unroll
        for (int k = 0; k < 8; k++) {
            float4 v4 = mrow[k];
            x[4 * k + 0] = v4.x; x[4 * k + 1] = v4.y;
            x[4 * k + 2] = v4.z; x[4 * k + 3] = v4.w;
            s  += v4.x + v4.y + v4.z + v4.w;
            sq += v4.x * v4.x + v4.y * v4.y + v4.z * v4.z + v4.w * v4.w;
        }
        // combine stats with partner lane
        s  += __shfl_xor_sync(0xffffffffu, s, 1);
        sq += __shfl_xor_sync(0xffffffffu, sq, 1);
        float mu = s * (1.f / CIN);
        float rs = rsqrtf(sq * (1.f / CIN) - mu * mu + 1e-5f);
#pragma unroll
        for (int c = 0; c < 32; c++)
            x[c] = (x[c] - mu) * rs * lnw_s[cbase + c] + lnb_s[cbase + c];

        float mv = mask[(size_t)n * NRES + r];
        if (!parity) macc += mv;
#pragma unroll
        for (int c = 0; c < 32; c++) qacc[c] += mv * x[c];

        // k/v projection: this lane's 32 channels into all 16 outputs
        ull a2[8];
#pragma unroll
        for (int j = 0; j < 8; j++) a2[j] = 0ull;
#pragma unroll
        for (int c = 0; c < 32; c++) {
            ull xc = dup2(x[c]);
            const ulonglong2* wr = (const ulonglong2*)(wkv_s + (cbase + c) * 16);
#pragma unroll
            for (int i2 = 0; i2 < 4; i2++) {
                ulonglong2 w2 = wr[i2];
                a2[2 * i2]     = fma2(xc, w2.x, a2[2 * i2]);
                a2[2 * i2 + 1] = fma2(xc, w2.y, a2[2 * i2 + 1]);
            }
        }
        // pair-sum -> both lanes have full k,v
#pragma unroll
        for (int j = 0; j < 8; j++) a2[j] = add2(a2[j], shfl64x(a2[j], 1));
        if (!parity) {
            ulonglong2* kp = (ulonglong2*)(g_k + ((size_t)r * NSEQ + n) * NC);
            ulonglong2 t0; t0.x = a2[0]; t0.y = a2[1]; kp[0] = t0;
            ulonglong2 t1; t1.x = a2[2]; t1.y = a2[3]; kp[1] = t1;
        } else {
            ulonglong2* vp = (ulonglong2*)(g_v + ((size_t)r * NSEQ + n) * NC);
            ulonglong2 t2; t2.x = a2[4]; t2.y = a2[5]; vp[0] = t2;
            ulonglong2 t3; t3.x = a2[6]; t3.y = a2[7]; vp[1] = t3;
        }
    }

    // qacc reduction: lanes of same parity within warp (offsets 2..16)
#pragma unroll
    for (int c = 0; c < 32; c++) {
        float v = qacc[c];
#pragma unroll
        for (int o = 16; o >= 2; o >>= 1) v += __shfl_xor_sync(0xffffffffu, v, o);
        qacc[c] = v;
    }
    float mt = wsum(macc);
    if (lane < 2) {
#pragma unroll
        for (int c = 0; c < 32; c++) qred[warp][lane * 32 + c] = qacc[c];
    }
    if (lane == 0) mred[warp] = mt;
    __syncthreads();
    if (tid < CIN) {
        float s2 = 0.f;
#pragma unroll
        for (int w = 0; w < 8; w++) s2 += qred[w][tid];
        g_qsum[r * CIN + tid] = s2;
    }
    if (tid == 0) {
        float s2 = 0.f;
#pragma unroll
        for (int w = 0; w < 8; w++) s2 += mred[w];
        g_msum[r] = s2;
    }
}

// =====================================================================
// Pass 2: per column r — q projection, logits, softmax, o accumulation.
// 512 threads = 256 row-slots x 2 head-halves (4 heads per thread).
// =====================================================================
__global__ void __launch_bounds__(512) pass2_kernel(
    const float* __restrict__ mask, const float* __restrict__ wq)
{
    const int r = blockIdx.x;
    const int tid = threadIdx.x;
    const int lane = tid & 31, warp = tid >> 5;
    const int slot = tid >> 1, hp = tid & 1;   // heads hp*4 .. hp*4+3

    __shared__ float qpre[CIN];
    __shared__ float qh[CIN];
    __shared__ float redm[16][NH];
    __shared__ float reds[16][NH];
    __shared__ float hmax_s[NH], hsum_s[NH];
    __shared__ float ored[16][CIN];

    if (tid < CIN) qpre[tid] = g_qsum[r * CIN + tid] / (g_msum[r] + 1e-10f);
    __syncthreads();
    if (tid < CIN) {
        float a = 0.f;
#pragma unroll
        for (int c = 0; c < CIN; c++) a += qpre[c] * wq[c * CIN + tid];
        qh[tid] = a * 0.3535533905932738f;   // C^-0.5
    }
    __syncthreads();

    float l[8][4];
    float hmax[4];
#pragma unroll
    for (int h = 0; h < 4; h++) hmax[h] = -3.4e38f;

#pragma unroll
    for (int i = 0; i < 8; i++) {
        int n = i * 256 + slot;
        const float4* kp = (const float4*)(g_k + ((size_t)r * NSEQ + n) * NC);
        float4 k0 = kp[0], k1 = kp[1];
        float bias = (mask[(size_t)n * NRES + r] - 1.f) * 1000000000.0f;
#pragma unroll
        for (int h = 0; h < 4; h++) {
            const float* q = qh + (hp * 4 + h) * NC;
            float a = q[0] * k0.x + q[1] * k0.y + q[2] * k0.z + q[3] * k0.w
                    + q[4] * k1.x + q[5] * k1.y + q[6] * k1.z + q[7] * k1.w;
            a += bias;
            l[i][h] = a;
            hmax[h] = fmaxf(hmax[h], a);
        }
    }
    // reduce max among same-hp lanes
#pragma unroll
    for (int h = 0; h < 4; h++) {
        float v = hmax[h];
#pragma unroll
        for (int o = 16; o >= 2; o >>= 1) v = fmaxf(v, __shfl_xor_sync(0xffffffffu, v, o));
        hmax[h] = v;
    }
    if (lane < 2) {
#pragma unroll
        for (int h = 0; h < 4; h++) redm[warp][lane * 4 + h] = hmax[h];
    }
    __syncthreads();
    if (tid < NH) {
        float v = -3.4e38f;
#pragma unroll
        for (int w = 0; w < 16; w++) v = fmaxf(v, redm[w][tid]);
        hmax_s[tid] = v;
    }
    __syncthreads();

    float hsum[4];
#pragma unroll
    for (int h = 0; h < 4; h++) hsum[h] = 0.f;
    float oacc[32];
#pragma unroll
    for (int j = 0; j < 32; j++) oacc[j] = 0.f;

#pragma unroll
    for (int i = 0; i < 8; i++) {
        int n = i * 256 + slot;
        const float4* vp = (const float4*)(g_v + ((size_t)r * NSEQ + n) * NC);
        float4 v0 = vp[0], v1 = vp[1];
#pragma unroll
        for (int h = 0; h < 4; h++) {
            float p = __expf(l[i][h] - hmax_s[hp * 4 + h]);
            hsum[h] += p;
            oacc[h * 8 + 0] += p * v0.x; oacc[h * 8 + 1] += p * v0.y;
            oacc[h * 8 + 2] += p * v0.z; oacc[h * 8 + 3] += p * v0.w;
            oacc[h * 8 + 4] += p * v1.x; oacc[h * 8 + 5] += p * v1.y;
            oacc[h * 8 + 6] += p * v1.z; oacc[h * 8 + 7] += p * v1.w;
        }
    }
#pragma unroll
    for (int h = 0; h < 4; h++) {
        float v = hsum[h];
#pragma unroll
        for (int o = 16; o >= 2; o >>= 1) v += __shfl_xor_sync(0xffffffffu, v, o);
        hsum[h] = v;
    }
#pragma unroll
    for (int j = 0; j < 32; j++) {
        float v = oacc[j];
#pragma unroll
        for (int o = 16; o >= 2; o >>= 1) v += __shfl_xor_sync(0xffffffffu, v, o);
        oacc[j] = v;
    }
    if (lane < 2) {
#pragma unroll
        for (int h = 0; h < 4; h++) reds[warp][lane * 4 + h] = hsum[h];
#pragma unroll
        for (int j = 0; j < 32; j++) ored[warp][lane * 32 + j] = oacc[j];
    }
    __syncthreads();
    if (tid < NH) {
        float v = 0.f;
#pragma unroll
        for (int w = 0; w < 16; w++) v += reds[w][tid];
        hsum_s[tid] = v;
    }
    __syncthreads();
    if (tid < CIN) {
        float s2 = 0.f;
#pragma unroll
        for (int w = 0; w < 16; w++) s2 += ored[w][tid];
        g_o[r * CIN + tid] = s2 / hsum_s[tid >> 3];
    }
}

// =====================================================================
// Pass 3 (hot): per (n,r) — layernorm, g = sigmoid(x@Wg + bg),
// out = (o*g) @ Wo + bo. 2 lanes per row, all FMA2, no spills.
// =====================================================================
__global__ void __launch_bounds__(256, 2) pass3_kernel(
    const float* __restrict__ m,
    const float* __restrict__ lnw, const float* __restrict__ lnb,
    const float* __restrict__ wg, const float* __restrict__ bg,
    const float* __restrict__ wo, const float* __restrict__ bo,
    float* __restrict__ out)
{
    const int r = blockIdx.x;
    const int tid = threadIdx.x;
    const int slot = tid >> 1, parity = tid & 1;
    const int cbase = parity * 32;
    const int n = blockIdx.y * 128 + slot;

    __shared__ __align__(16) float wg_s[CIN * CIN];
    __shared__ __align__(16) float wo_s[CIN * CIN];
    __shared__ __align__(16) float lnw_s[CIN], lnb_s[CIN];
    __shared__ __align__(16) float o_s[CIN];
    __shared__ __align__(16) float bg_s[CIN];
    __shared__ __align__(16) float bo_s[CIN];

    for (int i = tid; i < CIN * CIN; i += 256) { wg_s[i] = wg[i]; wo_s[i] = wo[i]; }
    if (tid < CIN) {
        lnw_s[tid] = lnw[tid]; lnb_s[tid] = lnb[tid];
        o_s[tid] = g_o[r * CIN + tid];
        bg_s[tid] = bg[tid]; bo_s[tid] = bo[tid];
    }
    __syncthreads();

    // ---- layernorm (lane owns 32 channels) ----
    const float4* mrow = (const float4*)(m + ((size_t)n * NRES + r) * CIN) + parity * 8;
    float x[32];
    {
        float s = 0.f, sq = 0.f;
#pragma unroll
        for (int k = 0; k < 8; k++) {
            float4 v4 = mrow[k];
            x[4 * k + 0] = v4.x; x[4 * k + 1] = v4.y;
            x[4 * k + 2] = v4.z; x[4 * k + 3] = v4.w;
            s  += v4.x + v4.y + v4.z + v4.w;
            sq += v4.x * v4.x + v4.y * v4.y + v4.z * v4.z + v4.w * v4.w;
        }
        s  += __shfl_xor_sync(0xffffffffu, s, 1);
        sq += __shfl_xor_sync(0xffffffffu, sq, 1);
        float mu = s * (1.f / CIN);
        float rs = rsqrtf(sq * (1.f / CIN) - mu * mu + 1e-5f);
#pragma unroll
        for (int c = 0; c < 32; c++)
            x[c] = (x[c] - mu) * rs * lnw_s[cbase + c] + lnb_s[cbase + c];
    }

    // ---- GEMM1 partials: ga[p] = sum over lane's 32 c of x[c]*wg[c][2p..2p+1] ----
    ull ga[32];
#pragma unroll
    for (int p = 0; p < 32; p++) ga[p] = 0ull;
#pragma unroll
    for (int c = 0; c < 32; c++) {
        ull xc = dup2(x[c]);
        const ulonglong2* wr = (const ulonglong2*)(wg_s + (cbase + c) * CIN);
#pragma unroll
        for (int i2 = 0; i2 < 16; i2++) {
            ulonglong2 w2 = wr[i2];
            ga[2 * i2]     = fma2(xc, w2.x, ga[2 * i2]);
            ga[2 * i2 + 1] = fma2(xc, w2.y, ga[2 * i2 + 1]);
        }
    }
    // pair exchange: lane0 keeps totals for p 0..15 (j 0..31), lane1 p 16..31
#pragma unroll
    for (int p = 0; p < 16; p++) {
        ull snd = parity ? ga[p] : ga[p + 16];
        ull rcv = shfl64x(snd, 1);
        if (!parity) ga[p] = add2(ga[p], rcv);
        else         ga[p + 16] = add2(ga[p + 16], rcv);
    }

    // gate: y[j] = o[j] * sigmoid(gpre[j] + bg[j]) for this lane's 32 j's
    float y[32];
    {
        const ull* bg2 = (const ull*)bg_s;
#pragma unroll
        for (int p = 0; p < 16; p++) {
            ull gp = parity ? ga[p + 16] : ga[p];
            float2 t = unpk(add2(gp, bg2[parity * 16 + p]));
            int j0 = parity * 32 + 2 * p;
            y[2 * p]     = o_s[j0]     / (1.f + __expf(-t.x));
            y[2 * p + 1] = o_s[j0 + 1] / (1.f + __expf(-t.y));
        }
    }

    // ---- GEMM2 partials over this lane's 32 j's into all 64 outputs ----
    ull oa[32];
#pragma unroll
    for (int p = 0; p < 32; p++) oa[p] = 0ull;
#pragma unroll
    for (int j = 0; j < 32; j++) {
        ull yd = dup2(y[j]);
        const ulonglong2* wr = (const ulonglong2*)(wo_s + (parity * 32 + j) * CIN);
#pragma unroll
        for (int i2 = 0; i2 < 16; i2++) {
            ulonglong2 w2 = wr[i2];
            oa[2 * i2]     = fma2(yd, w2.x, oa[2 * i2]);
            oa[2 * i2 + 1] = fma2(yd, w2.y, oa[2 * i2 + 1]);
        }
    }
    // pair exchange: lane0 keeps c 0..31 (p 0..15), lane1 c 32..63
#pragma unroll
    for (int p = 0; p < 16; p++) {
        ull snd = parity ? oa[p] : oa[p + 16];
        ull rcv = shfl64x(snd, 1);
        if (!parity) oa[p] = add2(oa[p], rcv);
        else         oa[p + 16] = add2(oa[p + 16], rcv);
    }

    // add bias, store this lane's 32 outputs (128B)
    {
        const ull* bo2 = (const ull*)bo_s;
        ulonglong2* op = (ulonglong2*)(out + ((size_t)n * NRES + r) * CIN + cbase);
#pragma unroll
        for (int q = 0; q < 8; q++) {
            ull a = parity ? oa[16 + 2 * q]     : oa[2 * q];
            ull b = parity ? oa[16 + 2 * q + 1] : oa[2 * q + 1];
            ulonglong2 t;
            t.x = add2(a, bo2[parity * 16 + 2 * q]);
            t.y = add2(b, bo2[parity * 16 + 2 * q + 1]);
            op[q] = t;
        }
    }
}

extern "C" void kernel_launch(void* const* d_in, const int* in_sizes, int n_in,
                              void* d_out, int out_size) {
    const float* m    = (const float*)d_in[0];
    const float* mask = (const float*)d_in[1];
    const float* lnw  = (const float*)d_in[2];
    const float* lnb  = (const float*)d_in[3];
    const float* wq   = (const float*)d_in[4];
    const float* wk   = (const float*)d_in[5];
    const float* wv   = (const float*)d_in[6];
    const float* wg   = (const float*)d_in[7];
    const float* bg   = (const float*)d_in[8];
    const float* wo   = (const float*)d_in[9];
    const float* bo   = (const float*)d_in[10];
    float* out = (float*)d_out;

    pass1_kernel<<<NRES, 256>>>(m, mask, lnw, lnb, wk, wv);
    pass2_kernel<<<NRES, 512>>>(mask, wq);
    pass3_kernel<<<dim3(NRES, NSEQ / 128), 256>>>(m, lnw, lnb, wg, bg, wo, bo, out);
}

// round 4
// speedup vs baseline: 1.6403x; 1.2812x over previous
#include <cuda_runtime.h>

typedef unsigned long long ull;

#define NSEQ 2048
#define NRES 512
#define CIN  64
#define NH   8
#define NC   8

// ---------------- scratch (device globals: allocation-free) ----------------
__device__ __align__(16) float g_k[(size_t)NRES * NSEQ * NC];     // 32 MB
__device__ __align__(16) float g_v[(size_t)NRES * NSEQ * NC];     // 32 MB
__device__ __align__(16) float g_qsum[NRES * CIN];
__device__ __align__(16) float g_msum[NRES];
__device__ __align__(16) float g_o[NRES * CIN];

// ---------------- packed f32x2 helpers ----------------
__device__ __forceinline__ ull fma2(ull a, ull b, ull c) {
    ull d;
    asm("fma.rn.f32x2 %0, %1, %2, %3;" : "=l"(d) : "l"(a), "l"(b), "l"(c));
    return d;
}
__device__ __forceinline__ ull add2(ull a, ull b) {
    ull d;
    asm("add.rn.f32x2 %0, %1, %2;" : "=l"(d) : "l"(a), "l"(b));
    return d;
}
__device__ __forceinline__ ull dup2(float x) {
    ull d; unsigned xi = __float_as_uint(x);
    asm("mov.b64 %0, {%1, %1};" : "=l"(d) : "r"(xi));
    return d;
}
__device__ __forceinline__ float2 unpk(ull a) {
    unsigned lo, hi;
    asm("mov.b64 {%0, %1}, %2;" : "=r"(lo), "=r"(hi) : "l"(a));
    return make_float2(__uint_as_float(lo), __uint_as_float(hi));
}
__device__ __forceinline__ ull shfl64x(ull v, int m) {
    return __shfl_xor_sync(0xffffffffu, v, m);
}
__device__ __forceinline__ float wsum(float v) {
#pragma unroll
    for (int o = 16; o; o >>= 1) v += __shfl_xor_sync(0xffffffffu, v, o);
    return v;
}

// =====================================================================
// Pass 1: per column r — layernorm, k/v projection, masked q-sum.
// (unchanged from R3)
// =====================================================================
__global__ void __launch_bounds__(256, 2) pass1_kernel(
    const float* __restrict__ m, const float* __restrict__ mask,
    const float* __restrict__ lnw, const float* __restrict__ lnb,
    const float* __restrict__ wk, const float* __restrict__ wv)
{
    const int r = blockIdx.x;
    const int tid = threadIdx.x;
    const int lane = tid & 31, warp = tid >> 5;
    const int slot = tid >> 1, parity = tid & 1;
    const int cbase = parity * 32;

    __shared__ __align__(16) float wkv_s[CIN * 16];
    __shared__ float lnw_s[CIN], lnb_s[CIN];
    __shared__ float qred[8][CIN];
    __shared__ float mred[8];

    for (int i = tid; i < CIN * 16; i += 256) {
        int c = i >> 4, j = i & 15;
        wkv_s[i] = (j < 8) ? wk[c * 8 + j] : wv[c * 8 + (j - 8)];
    }
    if (tid < CIN) { lnw_s[tid] = lnw[tid]; lnb_s[tid] = lnb[tid]; }
    __syncthreads();

    float qacc[32];
#pragma unroll
    for (int c = 0; c < 32; c++) qacc[c] = 0.f;
    float macc = 0.f;

    for (int it = 0; it < NSEQ / 128; it++) {
        const int n = it * 128 + slot;
        const float4* mrow = (const float4*)(m + ((size_t)n * NRES + r) * CIN) + parity * 8;
        float x[32];
        float s = 0.f, sq = 0.f;
#pragma unroll
        for (int k = 0; k < 8; k++) {
            float4 v4 = mrow[k];
            x[4 * k + 0] = v4.x; x[4 * k + 1] = v4.y;
            x[4 * k + 2] = v4.z; x[4 * k + 3] = v4.w;
            s  += v4.x + v4.y + v4.z + v4.w;
            sq += v4.x * v4.x + v4.y * v4.y + v4.z * v4.z + v4.w * v4.w;
        }
        s  += __shfl_xor_sync(0xffffffffu, s, 1);
        sq += __shfl_xor_sync(0xffffffffu, sq, 1);
        float mu = s * (1.f / CIN);
        float rs = rsqrtf(sq * (1.f / CIN) - mu * mu + 1e-5f);
#pragma unroll
        for (int c = 0; c < 32; c++)
            x[c] = (x[c] - mu) * rs * lnw_s[cbase + c] + lnb_s[cbase + c];

        float mv = mask[(size_t)n * NRES + r];
        if (!parity) macc += mv;
#pragma unroll
        for (int c = 0; c < 32; c++) qacc[c] += mv * x[c];

        ull a2[8];
#pragma unroll
        for (int j = 0; j < 8; j++) a2[j] = 0ull;
#pragma unroll
        for (int c = 0; c < 32; c++) {
            ull xc = dup2(x[c]);
            const ulonglong2* wr = (const ulonglong2*)(wkv_s + (cbase + c) * 16);
#pragma unroll
            for (int i2 = 0; i2 < 4; i2++) {
                ulonglong2 w2 = wr[i2];
                a2[2 * i2]     = fma2(xc, w2.x, a2[2 * i2]);
                a2[2 * i2 + 1] = fma2(xc, w2.y, a2[2 * i2 + 1]);
            }
        }
#pragma unroll
        for (int j = 0; j < 8; j++) a2[j] = add2(a2[j], shfl64x(a2[j], 1));
        if (!parity) {
            ulonglong2* kp = (ulonglong2*)(g_k + ((size_t)r * NSEQ + n) * NC);
            ulonglong2 t0; t0.x = a2[0]; t0.y = a2[1]; kp[0] = t0;
            ulonglong2 t1; t1.x = a2[2]; t1.y = a2[3]; kp[1] = t1;
        } else {
            ulonglong2* vp = (ulonglong2*)(g_v + ((size_t)r * NSEQ + n) * NC);
            ulonglong2 t2; t2.x = a2[4]; t2.y = a2[5]; vp[0] = t2;
            ulonglong2 t3; t3.x = a2[6]; t3.y = a2[7]; vp[1] = t3;
        }
    }

#pragma unroll
    for (int c = 0; c < 32; c++) {
        float v = qacc[c];
#pragma unroll
        for (int o = 16; o >= 2; o >>= 1) v += __shfl_xor_sync(0xffffffffu, v, o);
        qacc[c] = v;
    }
    float mt = wsum(macc);
    if (lane < 2) {
#pragma unroll
        for (int c = 0; c < 32; c++) qred[warp][lane * 32 + c] = qacc[c];
    }
    if (lane == 0) mred[warp] = mt;
    __syncthreads();
    if (tid < CIN) {
        float s2 = 0.f;
#pragma unroll
        for (int w = 0; w < 8; w++) s2 += qred[w][tid];
        g_qsum[r * CIN + tid] = s2;
    }
    if (tid == 0) {
        float s2 = 0.f;
#pragma unroll
        for (int w = 0; w < 8; w++) s2 += mred[w];
        g_msum[r] = s2;
    }
}

// =====================================================================
// Pass 2: per column r — q projection, logits, softmax, o accumulation.
// (unchanged from R3)
// =====================================================================
__global__ void __launch_bounds__(512) pass2_kernel(
    const float* __restrict__ mask, const float* __restrict__ wq)
{
    const int r = blockIdx.x;
    const int tid = threadIdx.x;
    const int lane = tid & 31, warp = tid >> 5;
    const int slot = tid >> 1, hp = tid & 1;

    __shared__ float qpre[CIN];
    __shared__ float qh[CIN];
    __shared__ float redm[16][NH];
    __shared__ float reds[16][NH];
    __shared__ float hmax_s[NH], hsum_s[NH];
    __shared__ float ored[16][CIN];

    if (tid < CIN) qpre[tid] = g_qsum[r * CIN + tid] / (g_msum[r] + 1e-10f);
    __syncthreads();
    if (tid < CIN) {
        float a = 0.f;
#pragma unroll
        for (int c = 0; c < CIN; c++) a += qpre[c] * wq[c * CIN + tid];
        qh[tid] = a * 0.3535533905932738f;
    }
    __syncthreads();

    float l[8][4];
    float hmax[4];
#pragma unroll
    for (int h = 0; h < 4; h++) hmax[h] = -3.4e38f;

#pragma unroll
    for (int i = 0; i < 8; i++) {
        int n = i * 256 + slot;
        const float4* kp = (const float4*)(g_k + ((size_t)r * NSEQ + n) * NC);
        float4 k0 = kp[0], k1 = kp[1];
        float bias = (mask[(size_t)n * NRES + r] - 1.f) * 1000000000.0f;
#pragma unroll
        for (int h = 0; h < 4; h++) {
            const float* q = qh + (hp * 4 + h) * NC;
            float a = q[0] * k0.x + q[1] * k0.y + q[2] * k0.z + q[3] * k0.w
                    + q[4] * k1.x + q[5] * k1.y + q[6] * k1.z + q[7] * k1.w;
            a += bias;
            l[i][h] = a;
            hmax[h] = fmaxf(hmax[h], a);
        }
    }
#pragma unroll
    for (int h = 0; h < 4; h++) {
        float v = hmax[h];
#pragma unroll
        for (int o = 16; o >= 2; o >>= 1) v = fmaxf(v, __shfl_xor_sync(0xffffffffu, v, o));
        hmax[h] = v;
    }
    if (lane < 2) {
#pragma unroll
        for (int h = 0; h < 4; h++) redm[warp][lane * 4 + h] = hmax[h];
    }
    __syncthreads();
    if (tid < NH) {
        float v = -3.4e38f;
#pragma unroll
        for (int w = 0; w < 16; w++) v = fmaxf(v, redm[w][tid]);
        hmax_s[tid] = v;
    }
    __syncthreads();

    float hsum[4];
#pragma unroll
    for (int h = 0; h < 4; h++) hsum[h] = 0.f;
    float oacc[32];
#pragma unroll
    for (int j = 0; j < 32; j++) oacc[j] = 0.f;

#pragma unroll
    for (int i = 0; i < 8; i++) {
        int n = i * 256 + slot;
        const float4* vp = (const float4*)(g_v + ((size_t)r * NSEQ + n) * NC);
        float4 v0 = vp[0], v1 = vp[1];
#pragma unroll
        for (int h = 0; h < 4; h++) {
            float p = __expf(l[i][h] - hmax_s[hp * 4 + h]);
            hsum[h] += p;
            oacc[h * 8 + 0] += p * v0.x; oacc[h * 8 + 1] += p * v0.y;
            oacc[h * 8 + 2] += p * v0.z; oacc[h * 8 + 3] += p * v0.w;
            oacc[h * 8 + 4] += p * v1.x; oacc[h * 8 + 5] += p * v1.y;
            oacc[h * 8 + 6] += p * v1.z; oacc[h * 8 + 7] += p * v1.w;
        }
    }
#pragma unroll
    for (int h = 0; h < 4; h++) {
        float v = hsum[h];
#pragma unroll
        for (int o = 16; o >= 2; o >>= 1) v += __shfl_xor_sync(0xffffffffu, v, o);
        hsum[h] = v;
    }
#pragma unroll
    for (int j = 0; j < 32; j++) {
        float v = oacc[j];
#pragma unroll
        for (int o = 16; o >= 2; o >>= 1) v += __shfl_xor_sync(0xffffffffu, v, o);
        oacc[j] = v;
    }
    if (lane < 2) {
#pragma unroll
        for (int h = 0; h < 4; h++) reds[warp][lane * 4 + h] = hsum[h];
#pragma unroll
        for (int j = 0; j < 32; j++) ored[warp][lane * 32 + j] = oacc[j];
    }
    __syncthreads();
    if (tid < NH) {
        float v = 0.f;
#pragma unroll
        for (int w = 0; w < 16; w++) v += reds[w][tid];
        hsum_s[tid] = v;
    }
    __syncthreads();
    if (tid < CIN) {
        float s2 = 0.f;
#pragma unroll
        for (int w = 0; w < 16; w++) s2 += ored[w][tid];
        g_o[r * CIN + tid] = s2 / hsum_s[tid >> 3];
    }
}

// =====================================================================
// Pass 3 (hot), rewritten: block = (r, 128 n-rows). LN -> smem X[k][row],
// register-blocked GEMM (8 rows x 8 cols x 32 k per thread, khalf pair),
// sigmoid-gate epilogue -> smem Y[j][row] -> second GEMM -> coalesced out.
// =====================================================================
#define P3_SMEM_FLOATS (8192 /*buf*/ + 4096 /*wg*/ + 4096 /*wo*/ + 64*5)
#define P3_SMEM_BYTES (P3_SMEM_FLOATS * 4)

__global__ void __launch_bounds__(256, 2) pass3_kernel(
    const float* __restrict__ m,
    const float* __restrict__ lnw, const float* __restrict__ lnb,
    const float* __restrict__ wg, const float* __restrict__ bg,
    const float* __restrict__ wo, const float* __restrict__ bo,
    float* __restrict__ out)
{
    extern __shared__ __align__(16) float sm[];
    float* buf  = sm;                 // 8192: X[k][128] -> Y[j][128] -> O[row][64]
    float* wg_s = sm + 8192;          // 4096
    float* wo_s = sm + 12288;         // 4096
    float* o_s  = sm + 16384;         // 64
    float* bg_s = o_s + 64;
    float* bo_s = bg_s + 64;
    float* lnw_s = bo_s + 64;
    float* lnb_s = lnw_s + 64;

    const int r = blockIdx.x;
    const int tid = threadIdx.x;

    for (int i = tid; i < CIN * CIN; i += 256) { wg_s[i] = wg[i]; wo_s[i] = wo[i]; }
    if (tid < CIN) {
        o_s[tid] = g_o[r * CIN + tid];
        bg_s[tid] = bg[tid]; bo_s[tid] = bo[tid];
        lnw_s[tid] = lnw[tid]; lnb_s[tid] = lnb[tid];
    }
    __syncthreads();

    // ---- Stage A: layernorm 128 rows into buf[k][row] (2 threads/row) ----
    {
        const int slot = tid >> 1, parity = tid & 1;
        const int cbase = parity * 32;
        const int n = blockIdx.y * 128 + slot;
        const float4* mrow = (const float4*)(m + ((size_t)n * NRES + r) * CIN) + parity * 8;
        float x[32];
        float s = 0.f, sq = 0.f;
#pragma unroll
        for (int k = 0; k < 8; k++) {
            float4 v4 = mrow[k];
            x[4 * k + 0] = v4.x; x[4 * k + 1] = v4.y;
            x[4 * k + 2] = v4.z; x[4 * k + 3] = v4.w;
            s  += v4.x + v4.y + v4.z + v4.w;
            sq += v4.x * v4.x + v4.y * v4.y + v4.z * v4.z + v4.w * v4.w;
        }
        s  += __shfl_xor_sync(0xffffffffu, s, 1);
        sq += __shfl_xor_sync(0xffffffffu, sq, 1);
        float mu = s * (1.f / CIN);
        float rs = rsqrtf(sq * (1.f / CIN) - mu * mu + 1e-5f);
#pragma unroll
        for (int c = 0; c < 32; c++)
            buf[(cbase + c) * 128 + slot] =
                (x[c] - mu) * rs * lnw_s[cbase + c] + lnb_s[cbase + c];
    }
    __syncthreads();

    // ---- GEMM thread mapping ----
    const int khalf  = tid & 1;
    const int colgrp = (tid >> 1) & 7;
    const int rowgrp = tid >> 4;
    const int rowbase = rowgrp * 8;
    const int colbase = colgrp * 8;
    const int kbase  = khalf * 32;

    ull acc[8][4];

    // ================= GEMM 1: gpre = X @ Wg =================
#pragma unroll
    for (int ri = 0; ri < 8; ri++)
#pragma unroll
        for (int cj = 0; cj < 4; cj++) acc[ri][cj] = 0ull;

#pragma unroll 4
    for (int kk = 0; kk < 32; kk++) {
        const int k = kbase + kk;
        const float4* xp = (const float4*)(buf + k * 128 + rowbase);
        float4 xa = xp[0], xb = xp[1];
        const ulonglong2* wp = (const ulonglong2*)(wg_s + k * CIN + colbase);
        ulonglong2 wA = wp[0], wB = wp[1];
        ull xd[8];
        xd[0] = dup2(xa.x); xd[1] = dup2(xa.y); xd[2] = dup2(xa.z); xd[3] = dup2(xa.w);
        xd[4] = dup2(xb.x); xd[5] = dup2(xb.y); xd[6] = dup2(xb.z); xd[7] = dup2(xb.w);
#pragma unroll
        for (int ri = 0; ri < 8; ri++) {
            acc[ri][0] = fma2(xd[ri], wA.x, acc[ri][0]);
            acc[ri][1] = fma2(xd[ri], wA.y, acc[ri][1]);
            acc[ri][2] = fma2(xd[ri], wB.x, acc[ri][2]);
            acc[ri][3] = fma2(xd[ri], wB.y, acc[ri][3]);
        }
    }
    // khalf pairwise reduction
#pragma unroll
    for (int ri = 0; ri < 8; ri++)
#pragma unroll
        for (int cj = 0; cj < 4; cj++)
            acc[ri][cj] = add2(acc[ri][cj], shfl64x(acc[ri][cj], 1));

    __syncthreads();   // all X reads done before overwriting buf with Y

    // epilogue 1: bias + sigmoid-gate, write Y[j][row]; khalf splits cols
    {
        const ull* bg2 = (const ull*)bg_s;
#pragma unroll
        for (int t = 0; t < 2; t++) {
            const int cj = khalf * 2 + t;
            const int col = colbase + cj * 2;
            const ull bpair = bg2[col >> 1];
#pragma unroll
            for (int ri = 0; ri < 8; ri++) {
                float2 g = unpk(add2(acc[ri][cj], bpair));
                buf[col * 128 + rowbase + ri]       = o_s[col]     / (1.f + __expf(-g.x));
                buf[(col + 1) * 128 + rowbase + ri] = o_s[col + 1] / (1.f + __expf(-g.y));
            }
        }
    }
    __syncthreads();

    // ================= GEMM 2: out = Y @ Wo =================
#pragma unroll
    for (int ri = 0; ri < 8; ri++)
#pragma unroll
        for (int cj = 0; cj < 4; cj++) acc[ri][cj] = 0ull;

#pragma unroll 4
    for (int kk = 0; kk < 32; kk++) {
        const int k = kbase + kk;
        const float4* yp = (const float4*)(buf + k * 128 + rowbase);
        float4 ya = yp[0], yb = yp[1];
        const ulonglong2* wp = (const ulonglong2*)(wo_s + k * CIN + colbase);
        ulonglong2 wA = wp[0], wB = wp[1];
        ull yd[8];
        yd[0] = dup2(ya.x); yd[1] = dup2(ya.y); yd[2] = dup2(ya.z); yd[3] = dup2(ya.w);
        yd[4] = dup2(yb.x); yd[5] = dup2(yb.y); yd[6] = dup2(yb.z); yd[7] = dup2(yb.w);
#pragma unroll
        for (int ri = 0; ri < 8; ri++) {
            acc[ri][0] = fma2(yd[ri], wA.x, acc[ri][0]);
            acc[ri][1] = fma2(yd[ri], wA.y, acc[ri][1]);
            acc[ri][2] = fma2(yd[ri], wB.x, acc[ri][2]);
            acc[ri][3] = fma2(yd[ri], wB.y, acc[ri][3]);
        }
    }
#pragma unroll
    for (int ri = 0; ri < 8; ri++)
#pragma unroll
        for (int cj = 0; cj < 4; cj++)
            acc[ri][cj] = add2(acc[ri][cj], shfl64x(acc[ri][cj], 1));

    __syncthreads();   // all Y reads done before overwriting buf with O

    // epilogue 2: bias, write O[row][col] to smem
    {
        const ull* bo2 = (const ull*)bo_s;
#pragma unroll
        for (int t = 0; t < 2; t++) {
            const int cj = khalf * 2 + t;
            const int col = colbase + cj * 2;
            const ull bpair = bo2[col >> 1];
#pragma unroll
            for (int ri = 0; ri < 8; ri++) {
                float2 v = unpk(add2(acc[ri][cj], bpair));
                buf[(rowbase + ri) * CIN + col]     = v.x;
                buf[(rowbase + ri) * CIN + col + 1] = v.y;
            }
        }
    }
    __syncthreads();

    // coalesced copy to global: 128 rows x 16 float4
    {
        const int n0 = blockIdx.y * 128;
        const float4* b4 = (const float4*)buf;
        for (int i = tid; i < 2048; i += 256) {
            const int row = i >> 4;
            const int c4  = i & 15;
            ((float4*)(out + ((size_t)(n0 + row) * NRES + r) * CIN))[c4] = b4[i];
        }
    }
}

extern "C" void kernel_launch(void* const* d_in, const int* in_sizes, int n_in,
                              void* d_out, int out_size) {
    const float* m    = (const float*)d_in[0];
    const float* mask = (const float*)d_in[1];
    const float* lnw  = (const float*)d_in[2];
    const float* lnb  = (const float*)d_in[3];
    const float* wq   = (const float*)d_in[4];
    const float* wk   = (const float*)d_in[5];
    const float* wv   = (const float*)d_in[6];
    const float* wg   = (const float*)d_in[7];
    const float* bg   = (const float*)d_in[8];
    const float* wo   = (const float*)d_in[9];
    const float* bo   = (const float*)d_in[10];
    float* out = (float*)d_out;

    cudaFuncSetAttribute(pass3_kernel,
                         cudaFuncAttributeMaxDynamicSharedMemorySize, P3_SMEM_BYTES);

    pass1_kernel<<<NRES, 256>>>(m, mask, lnw, lnb, wk, wv);
    pass2_kernel<<<NRES, 512>>>(mask, wq);
    pass3_kernel<<<dim3(NRES, NSEQ / 128), 256, P3_SMEM_BYTES>>>(
        m, lnw, lnb, wg, bg, wo, bo, out);
}

// round 5
// speedup vs baseline: 1.8761x; 1.1437x over previous
#include <cuda_runtime.h>

typedef unsigned long long ull;

#define NSEQ 2048
#define NRES 512
#define CIN  64
#define NH   8
#define NC   8

// ---------------- scratch (device globals: allocation-free) ----------------
__device__ __align__(16) float g_k[(size_t)NRES * NSEQ * NC];     // 32 MB
__device__ __align__(16) float g_v[(size_t)NRES * NSEQ * NC];     // 32 MB
__device__ __align__(16) float g_qsum[NRES * CIN];
__device__ __align__(16) float g_msum[NRES];
__device__ __align__(16) float g_o[NRES * CIN];

// ---------------- packed f32x2 helpers ----------------
__device__ __forceinline__ ull fma2(ull a, ull b, ull c) {
    ull d;
    asm("fma.rn.f32x2 %0, %1, %2, %3;" : "=l"(d) : "l"(a), "l"(b), "l"(c));
    return d;
}
__device__ __forceinline__ ull add2(ull a, ull b) {
    ull d;
    asm("add.rn.f32x2 %0, %1, %2;" : "=l"(d) : "l"(a), "l"(b));
    return d;
}
__device__ __forceinline__ ull dup2(float x) {
    ull d; unsigned xi = __float_as_uint(x);
    asm("mov.b64 %0, {%1, %1};" : "=l"(d) : "r"(xi));
    return d;
}
__device__ __forceinline__ ull pack2(float lo, float hi) {
    ull d;
    asm("mov.b64 %0, {%1, %2};" : "=l"(d) : "r"(__float_as_uint(lo)), "r"(__float_as_uint(hi)));
    return d;
}
__device__ __forceinline__ float2 unpk(ull a) {
    unsigned lo, hi;
    asm("mov.b64 {%0, %1}, %2;" : "=r"(lo), "=r"(hi) : "l"(a));
    return make_float2(__uint_as_float(lo), __uint_as_float(hi));
}
__device__ __forceinline__ ull shfl64x(ull v, int m) {
    return __shfl_xor_sync(0xffffffffu, v, m);
}
__device__ __forceinline__ float wsum(float v) {
#pragma unroll
    for (int o = 16; o; o >>= 1) v += __shfl_xor_sync(0xffffffffu, v, o);
    return v;
}

// =====================================================================
// Pass 1: per column r — layernorm, k/v projection, masked q-sum.
// (unchanged)
// =====================================================================
__global__ void __launch_bounds__(256, 2) pass1_kernel(
    const float* __restrict__ m, const float* __restrict__ mask,
    const float* __restrict__ lnw, const float* __restrict__ lnb,
    const float* __restrict__ wk, const float* __restrict__ wv)
{
    const int r = blockIdx.x;
    const int tid = threadIdx.x;
    const int lane = tid & 31, warp = tid >> 5;
    const int slot = tid >> 1, parity = tid & 1;
    const int cbase = parity * 32;

    __shared__ __align__(16) float wkv_s[CIN * 16];
    __shared__ float lnw_s[CIN], lnb_s[CIN];
    __shared__ float qred[8][CIN];
    __shared__ float mred[8];

    for (int i = tid; i < CIN * 16; i += 256) {
        int c = i >> 4, j = i & 15;
        wkv_s[i] = (j < 8) ? wk[c * 8 + j] : wv[c * 8 + (j - 8)];
    }
    if (tid < CIN) { lnw_s[tid] = lnw[tid]; lnb_s[tid] = lnb[tid]; }
    __syncthreads();

    float qacc[32];
#pragma unroll
    for (int c = 0; c < 32; c++) qacc[c] = 0.f;
    float macc = 0.f;

    for (int it = 0; it < NSEQ / 128; it++) {
        const int n = it * 128 + slot;
        const float4* mrow = (const float4*)(m + ((size_t)n * NRES + r) * CIN) + parity * 8;
        float x[32];
        float s = 0.f, sq = 0.f;
#pragma unroll
        for (int k = 0; k < 8; k++) {
            float4 v4 = mrow[k];
            x[4 * k + 0] = v4.x; x[4 * k + 1] = v4.y;
            x[4 * k + 2] = v4.z; x[4 * k + 3] = v4.w;
            s  += v4.x + v4.y + v4.z + v4.w;
            sq += v4.x * v4.x + v4.y * v4.y + v4.z * v4.z + v4.w * v4.w;
        }
        s  += __shfl_xor_sync(0xffffffffu, s, 1);
        sq += __shfl_xor_sync(0xffffffffu, sq, 1);
        float mu = s * (1.f / CIN);
        float rs = rsqrtf(sq * (1.f / CIN) - mu * mu + 1e-5f);
#pragma unroll
        for (int c = 0; c < 32; c++)
            x[c] = (x[c] - mu) * rs * lnw_s[cbase + c] + lnb_s[cbase + c];

        float mv = mask[(size_t)n * NRES + r];
        if (!parity) macc += mv;
#pragma unroll
        for (int c = 0; c < 32; c++) qacc[c] += mv * x[c];

        ull a2[8];
#pragma unroll
        for (int j = 0; j < 8; j++) a2[j] = 0ull;
#pragma unroll
        for (int c = 0; c < 32; c++) {
            ull xc = dup2(x[c]);
            const ulonglong2* wr = (const ulonglong2*)(wkv_s + (cbase + c) * 16);
#pragma unroll
            for (int i2 = 0; i2 < 4; i2++) {
                ulonglong2 w2 = wr[i2];
                a2[2 * i2]     = fma2(xc, w2.x, a2[2 * i2]);
                a2[2 * i2 + 1] = fma2(xc, w2.y, a2[2 * i2 + 1]);
            }
        }
#pragma unroll
        for (int j = 0; j < 8; j++) a2[j] = add2(a2[j], shfl64x(a2[j], 1));
        if (!parity) {
            ulonglong2* kp = (ulonglong2*)(g_k + ((size_t)r * NSEQ + n) * NC);
            ulonglong2 t0; t0.x = a2[0]; t0.y = a2[1]; kp[0] = t0;
            ulonglong2 t1; t1.x = a2[2]; t1.y = a2[3]; kp[1] = t1;
        } else {
            ulonglong2* vp = (ulonglong2*)(g_v + ((size_t)r * NSEQ + n) * NC);
            ulonglong2 t2; t2.x = a2[4]; t2.y = a2[5]; vp[0] = t2;
            ulonglong2 t3; t3.x = a2[6]; t3.y = a2[7]; vp[1] = t3;
        }
    }

#pragma unroll
    for (int c = 0; c < 32; c++) {
        float v = qacc[c];
#pragma unroll
        for (int o = 16; o >= 2; o >>= 1) v += __shfl_xor_sync(0xffffffffu, v, o);
        qacc[c] = v;
    }
    float mt = wsum(macc);
    if (lane < 2) {
#pragma unroll
        for (int c = 0; c < 32; c++) qred[warp][lane * 32 + c] = qacc[c];
    }
    if (lane == 0) mred[warp] = mt;
    __syncthreads();
    if (tid < CIN) {
        float s2 = 0.f;
#pragma unroll
        for (int w = 0; w < 8; w++) s2 += qred[w][tid];
        g_qsum[r * CIN + tid] = s2;
    }
    if (tid == 0) {
        float s2 = 0.f;
#pragma unroll
        for (int w = 0; w < 8; w++) s2 += mred[w];
        g_msum[r] = s2;
    }
}

// =====================================================================
// Pass 2: per column r — q projection, logits, softmax, o accumulation.
// (unchanged)
// =====================================================================
__global__ void __launch_bounds__(512) pass2_kernel(
    const float* __restrict__ mask, const float* __restrict__ wq)
{
    const int r = blockIdx.x;
    const int tid = threadIdx.x;
    const int lane = tid & 31, warp = tid >> 5;
    const int slot = tid >> 1, hp = tid & 1;

    __shared__ float qpre[CIN];
    __shared__ float qh[CIN];
    __shared__ float redm[16][NH];
    __shared__ float reds[16][NH];
    __shared__ float hmax_s[NH], hsum_s[NH];
    __shared__ float ored[16][CIN];

    if (tid < CIN) qpre[tid] = g_qsum[r * CIN + tid] / (g_msum[r] + 1e-10f);
    __syncthreads();
    if (tid < CIN) {
        float a = 0.f;
#pragma unroll
        for (int c = 0; c < CIN; c++) a += qpre[c] * wq[c * CIN + tid];
        qh[tid] = a * 0.3535533905932738f;
    }
    __syncthreads();

    float l[8][4];
    float hmax[4];
#pragma unroll
    for (int h = 0; h < 4; h++) hmax[h] = -3.4e38f;

#pragma unroll
    for (int i = 0; i < 8; i++) {
        int n = i * 256 + slot;
        const float4* kp = (const float4*)(g_k + ((size_t)r * NSEQ + n) * NC);
        float4 k0 = kp[0], k1 = kp[1];
        float bias = (mask[(size_t)n * NRES + r] - 1.f) * 1000000000.0f;
#pragma unroll
        for (int h = 0; h < 4; h++) {
            const float* q = qh + (hp * 4 + h) * NC;
            float a = q[0] * k0.x + q[1] * k0.y + q[2] * k0.z + q[3] * k0.w
                    + q[4] * k1.x + q[5] * k1.y + q[6] * k1.z + q[7] * k1.w;
            a += bias;
            l[i][h] = a;
            hmax[h] = fmaxf(hmax[h], a);
        }
    }
#pragma unroll
    for (int h = 0; h < 4; h++) {
        float v = hmax[h];
#pragma unroll
        for (int o = 16; o >= 2; o >>= 1) v = fmaxf(v, __shfl_xor_sync(0xffffffffu, v, o));
        hmax[h] = v;
    }
    if (lane < 2) {
#pragma unroll
        for (int h = 0; h < 4; h++) redm[warp][lane * 4 + h] = hmax[h];
    }
    __syncthreads();
    if (tid < NH) {
        float v = -3.4e38f;
#pragma unroll
        for (int w = 0; w < 16; w++) v = fmaxf(v, redm[w][tid]);
        hmax_s[tid] = v;
    }
    __syncthreads();

    float hsum[4];
#pragma unroll
    for (int h = 0; h < 4; h++) hsum[h] = 0.f;
    float oacc[32];
#pragma unroll
    for (int j = 0; j < 32; j++) oacc[j] = 0.f;

#pragma unroll
    for (int i = 0; i < 8; i++) {
        int n = i * 256 + slot;
        const float4* vp = (const float4*)(g_v + ((size_t)r * NSEQ + n) * NC);
        float4 v0 = vp[0], v1 = vp[1];
#pragma unroll
        for (int h = 0; h < 4; h++) {
            float p = __expf(l[i][h] - hmax_s[hp * 4 + h]);
            hsum[h] += p;
            oacc[h * 8 + 0] += p * v0.x; oacc[h * 8 + 1] += p * v0.y;
            oacc[h * 8 + 2] += p * v0.z; oacc[h * 8 + 3] += p * v0.w;
            oacc[h * 8 + 4] += p * v1.x; oacc[h * 8 + 5] += p * v1.y;
            oacc[h * 8 + 6] += p * v1.z; oacc[h * 8 + 7] += p * v1.w;
        }
    }
#pragma unroll
    for (int h = 0; h < 4; h++) {
        float v = hsum[h];
#pragma unroll
        for (int o = 16; o >= 2; o >>= 1) v += __shfl_xor_sync(0xffffffffu, v, o);
        hsum[h] = v;
    }
#pragma unroll
    for (int j = 0; j < 32; j++) {
        float v = oacc[j];
#pragma unroll
        for (int o = 16; o >= 2; o >>= 1) v += __shfl_xor_sync(0xffffffffu, v, o);
        oacc[j] = v;
    }
    if (lane < 2) {
#pragma unroll
        for (int h = 0; h < 4; h++) reds[warp][lane * 4 + h] = hsum[h];
#pragma unroll
        for (int j = 0; j < 32; j++) ored[warp][lane * 32 + j] = oacc[j];
    }
    __syncthreads();
    if (tid < NH) {
        float v = 0.f;
#pragma unroll
        for (int w = 0; w < 16; w++) v += reds[w][tid];
        hsum_s[tid] = v;
    }
    __syncthreads();
    if (tid < CIN) {
        float s2 = 0.f;
#pragma unroll
        for (int w = 0; w < 16; w++) s2 += ored[w][tid];
        g_o[r * CIN + tid] = s2 / hsum_s[tid >> 3];
    }
}

// =====================================================================
// Pass 3 v3 (hot): block = (r, 256 n-rows), 256 threads, 1 CTA/SM.
// Thread tile 8 rows x 8 cols x 64 k. Row-pair-packed accumulators:
//   x loads come packed from smem (no movs), weights pre-duplicated
//   into grouped layout (conflict-free LDS.128).
// buf (64KB) holds X[k][256], then Y (row-swizzled), then nothing
// (epilogue 2 stores directly to global).
// =====================================================================
#define P3_SMEM_FLOATS (16384 /*buf*/ + 8192 /*wg2*/ + 8192 /*wo2*/ + 320)
#define P3_SMEM_BYTES  (P3_SMEM_FLOATS * 4)

__global__ void __launch_bounds__(256, 1) pass3_kernel(
    const float* __restrict__ m,
    const float* __restrict__ lnw, const float* __restrict__ lnb,
    const float* __restrict__ wg, const float* __restrict__ bg,
    const float* __restrict__ wo, const float* __restrict__ bo,
    float* __restrict__ out)
{
    extern __shared__ __align__(16) float sm[];
    float* buf  = sm;                              // 16384 floats
    ull*   wg2  = (ull*)(sm + 16384);              // 4096 ull (dup'd, grouped)
    ull*   wo2  = (ull*)(sm + 24576);              // 4096 ull
    float* o_s  = sm + 32768;
    float* bg_s = o_s + 64;
    float* bo_s = bg_s + 64;
    float* lnw_s = bo_s + 64;
    float* lnb_s = lnw_s + 64;

    const int r   = blockIdx.x;
    const int tid = threadIdx.x;
    const int n0  = blockIdx.y * 256;

    // ---- weight prep: duplicate into grouped layout ----
    // chunk addressing: ull q = k*64 + (i*8 + colgrp)*2 + e,
    // holds dup2(w[k][colgrp*8 + 2*i + e]).
    for (int q = tid; q < 4096; q += 256) {
        int k  = q >> 6, rem = q & 63;
        int e  = rem & 1, ig = rem >> 1;
        int i  = ig >> 3, cg = ig & 7;
        int col = cg * 8 + 2 * i + e;
        wg2[q] = dup2(wg[k * CIN + col]);
        wo2[q] = dup2(wo[k * CIN + col]);
    }
    if (tid < CIN) {
        o_s[tid]  = g_o[r * CIN + tid];
        bg_s[tid] = bg[tid]; bo_s[tid] = bo[tid];
        lnw_s[tid] = lnw[tid]; lnb_s[tid] = lnb[tid];
    }
    __syncthreads();

    // ---- Stage A: layernorm one row per thread -> buf[k][row] ----
    {
        const float4* mrow = (const float4*)(m + ((size_t)(n0 + tid) * NRES + r) * CIN);
        float x[CIN];
        float s = 0.f, sq = 0.f;
#pragma unroll
        for (int k = 0; k < 16; k++) {
            float4 v4 = mrow[k];
            x[4 * k + 0] = v4.x; x[4 * k + 1] = v4.y;
            x[4 * k + 2] = v4.z; x[4 * k + 3] = v4.w;
            s  += v4.x + v4.y + v4.z + v4.w;
            sq += v4.x * v4.x + v4.y * v4.y + v4.z * v4.z + v4.w * v4.w;
        }
        float mu = s * (1.f / CIN);
        float rs = rsqrtf(sq * (1.f / CIN) - mu * mu + 1e-5f);
#pragma unroll
        for (int c = 0; c < CIN; c++)
            buf[c * 256 + tid] = (x[c] - mu) * rs * lnw_s[c] + lnb_s[c];
    }
    __syncthreads();

    const int rowbase = (tid >> 3) * 8;   // 0..248
    const int colgrp  = tid & 7;
    const int colbase = colgrp * 8;
    const ulonglong2* W;

    ull acc[4][8];

    // ================= GEMM 1: gpre = X @ Wg =================
#pragma unroll
    for (int rp = 0; rp < 4; rp++)
#pragma unroll
        for (int c = 0; c < 8; c++) acc[rp][c] = 0ull;

    W = (const ulonglong2*)wg2;
#pragma unroll 2
    for (int k = 0; k < CIN; k++) {
        const ulonglong2* xp = (const ulonglong2*)(buf + k * 256 + rowbase);
        ulonglong2 x0 = xp[0], x1 = xp[1];
        ulonglong2 w0 = W[k * 32 + colgrp];
        ulonglong2 w1 = W[k * 32 + colgrp + 8];
        ulonglong2 w2 = W[k * 32 + colgrp + 16];
        ulonglong2 w3 = W[k * 32 + colgrp + 24];
        ull xs0 = x0.x, xs1 = x0.y, xs2 = x1.x, xs3 = x1.y;
#pragma unroll
        for (int c = 0; c < 8; c++) {
            ull wv = (c == 0) ? w0.x : (c == 1) ? w0.y : (c == 2) ? w1.x : (c == 3) ? w1.y
                   : (c == 4) ? w2.x : (c == 5) ? w2.y : (c == 6) ? w3.x : w3.y;
            acc[0][c] = fma2(xs0, wv, acc[0][c]);
            acc[1][c] = fma2(xs1, wv, acc[1][c]);
            acc[2][c] = fma2(xs2, wv, acc[2][c]);
            acc[3][c] = fma2(xs3, wv, acc[3][c]);
        }
    }
    __syncthreads();   // all X reads done before Y overwrites buf

    // ---- epilogue 1: y = o * sigmoid(gpre + bg), store row-swizzled Y ----
    {
        const int sc = colgrp << 2;      // (col>>3)<<2 == colgrp<<2
#pragma unroll
        for (int c = 0; c < 8; c++) {
            const int col = colbase + c;
            const float bgc = bg_s[col];
            const float oc  = o_s[col];
#pragma unroll
            for (int rp = 0; rp < 4; rp++) {
                float2 t = unpk(acc[rp][c]);
                float y0 = oc / (1.f + __expf(-(t.x + bgc)));
                float y1 = oc / (1.f + __expf(-(t.y + bgc)));
                const int row = rowbase + 2 * rp;
                *(ull*)(buf + col * 256 + (row ^ sc)) = pack2(y0, y1);
            }
        }
    }
    __syncthreads();

    // ================= GEMM 2: out = Y @ Wo =================
#pragma unroll
    for (int rp = 0; rp < 4; rp++)
#pragma unroll
        for (int c = 0; c < 8; c++) acc[rp][c] = 0ull;

    W = (const ulonglong2*)wo2;
#pragma unroll 2
    for (int k = 0; k < CIN; k++) {
        const int sc = ((k >> 3) & 7) << 2;
        ulonglong2 x0 = *(const ulonglong2*)(buf + k * 256 + (rowbase ^ sc));
        ulonglong2 x1 = *(const ulonglong2*)(buf + k * 256 + ((rowbase + 4) ^ sc));
        ulonglong2 w0 = W[k * 32 + colgrp];
        ulonglong2 w1 = W[k * 32 + colgrp + 8];
        ulonglong2 w2 = W[k * 32 + colgrp + 16];
        ulonglong2 w3 = W[k * 32 + colgrp + 24];
        ull xs0 = x0.x, xs1 = x0.y, xs2 = x1.x, xs3 = x1.y;
#pragma unroll
        for (int c = 0; c < 8; c++) {
            ull wv = (c == 0) ? w0.x : (c == 1) ? w0.y : (c == 2) ? w1.x : (c == 3) ? w1.y
                   : (c == 4) ? w2.x : (c == 5) ? w2.y : (c == 6) ? w3.x : w3.y;
            acc[0][c] = fma2(xs0, wv, acc[0][c]);
            acc[1][c] = fma2(xs1, wv, acc[1][c]);
            acc[2][c] = fma2(xs2, wv, acc[2][c]);
            acc[3][c] = fma2(xs3, wv, acc[3][c]);
        }
    }

    // ---- epilogue 2: add bias, store directly to global ----
#pragma unroll
    for (int rp = 0; rp < 4; rp++) {
        float2 t[8];
#pragma unroll
        for (int c = 0; c < 8; c++) t[c] = unpk(acc[rp][c]);
#pragma unroll
        for (int e = 0; e < 2; e++) {
            const int row = rowbase + 2 * rp + e;
            float4 v0, v1;
            v0.x = (e ? t[0].y : t[0].x) + bo_s[colbase + 0];
            v0.y = (e ? t[1].y : t[1].x) + bo_s[colbase + 1];
            v0.z = (e ? t[2].y : t[2].x) + bo_s[colbase + 2];
            v0.w = (e ? t[3].y : t[3].x) + bo_s[colbase + 3];
            v1.x = (e ? t[4].y : t[4].x) + bo_s[colbase + 4];
            v1.y = (e ? t[5].y : t[5].x) + bo_s[colbase + 5];
            v1.z = (e ? t[6].y : t[6].x) + bo_s[colbase + 6];
            v1.w = (e ? t[7].y : t[7].x) + bo_s[colbase + 7];
            float4* dst = (float4*)(out + ((size_t)(n0 + row) * NRES + r) * CIN + colbase);
            dst[0] = v0;
            dst[1] = v1;
        }
    }
}

extern "C" void kernel_launch(void* const* d_in, const int* in_sizes, int n_in,
                              void* d_out, int out_size) {
    const float* m    = (const float*)d_in[0];
    const float* mask = (const float*)d_in[1];
    const float* lnw  = (const float*)d_in[2];
    const float* lnb  = (const float*)d_in[3];
    const float* wq   = (const float*)d_in[4];
    const float* wk   = (const float*)d_in[5];
    const float* wv   = (const float*)d_in[6];
    const float* wg   = (const float*)d_in[7];
    const float* bg   = (const float*)d_in[8];
    const float* wo   = (const float*)d_in[9];
    const float* bo   = (const float*)d_in[10];
    float* out = (float*)d_out;

    cudaFuncSetAttribute(pass3_kernel,
                         cudaFuncAttributeMaxDynamicSharedMemorySize, P3_SMEM_BYTES);

    pass1_kernel<<<NRES, 256>>>(m, mask, lnw, lnb, wk, wv);
    pass2_kernel<<<NRES, 512>>>(mask, wq);
    pass3_kernel<<<dim3(NRES, NSEQ / 256), 256, P3_SMEM_BYTES>>>(
        m, lnw, lnb, wg, bg, wo, bo, out);
}

// round 6
// speedup vs baseline: 2.1456x; 1.1436x over previous
#include <cuda_runtime.h>

typedef unsigned long long ull;

#define NSEQ 2048
#define NRES 512
#define CIN  64
#define NH   8
#define NC   8

// ---------------- scratch (device globals: allocation-free) ----------------
__device__ __align__(16) float g_k[(size_t)NRES * NSEQ * NC];     // 32 MB
__device__ __align__(16) float g_v[(size_t)NRES * NSEQ * NC];     // 32 MB
__device__ __align__(16) float g_qpart[NRES * 16 * CIN];
__device__ __align__(16) float g_mpart[NRES * 16];
__device__ __align__(16) float g_o[NRES * CIN];

// ---------------- packed f32x2 helpers ----------------
__device__ __forceinline__ ull fma2(ull a, ull b, ull c) {
    ull d;
    asm("fma.rn.f32x2 %0, %1, %2, %3;" : "=l"(d) : "l"(a), "l"(b), "l"(c));
    return d;
}
__device__ __forceinline__ ull dup2(float x) {
    ull d; unsigned xi = __float_as_uint(x);
    asm("mov.b64 %0, {%1, %1};" : "=l"(d) : "r"(xi));
    return d;
}
__device__ __forceinline__ ull pack2(float lo, float hi) {
    ull d;
    asm("mov.b64 %0, {%1, %2};" : "=l"(d) : "r"(__float_as_uint(lo)), "r"(__float_as_uint(hi)));
    return d;
}
__device__ __forceinline__ float2 unpk(ull a) {
    unsigned lo, hi;
    asm("mov.b64 {%0, %1}, %2;" : "=r"(lo), "=r"(hi) : "l"(a));
    return make_float2(__uint_as_float(lo), __uint_as_float(hi));
}
__device__ __forceinline__ float wsum(float v) {
#pragma unroll
    for (int o = 16; o; o >>= 1) v += __shfl_xor_sync(0xffffffffu, v, o);
    return v;
}

// =====================================================================
// Pass 1 v2: block = (r, 128 n-rows). Stage A: LN (2 thr/row) -> smem
// X[k][128], masked q-sum partials. Stage B: smem GEMM [128x16] for k/v
// (thread tile 8 rows x 1 col), coalesced kv store via smem staging.
// =====================================================================
__global__ void __launch_bounds__(256, 2) pass1_kernel(
    const float* __restrict__ m, const float* __restrict__ mask,
    const float* __restrict__ lnw, const float* __restrict__ lnb,
    const float* __restrict__ wk, const float* __restrict__ wv)
{
    __shared__ __align__(16) float buf[CIN * 128];    // X[k][row]  32 KB
    __shared__ __align__(16) float wkv_s[CIN * 16];   // 4 KB
    __shared__ __align__(16) float kv_s[128 * 16];    // 8 KB
    __shared__ float lnw_s[CIN], lnb_s[CIN];
    __shared__ float qred[8][CIN];
    __shared__ float mred[8];

    const int r   = blockIdx.x;
    const int by  = blockIdx.y;
    const int n0  = by * 128;
    const int tid = threadIdx.x;
    const int lane = tid & 31, warp = tid >> 5;

    for (int i = tid; i < CIN * 16; i += 256) {
        int c = i >> 4, j = i & 15;
        wkv_s[i] = (j < 8) ? wk[c * 8 + j] : wv[c * 8 + (j - 8)];
    }
    if (tid < CIN) { lnw_s[tid] = lnw[tid]; lnb_s[tid] = lnb[tid]; }
    __syncthreads();

    // ---- Stage A: layernorm + masked q-sum partial ----
    {
        const int slot = tid >> 1, parity = tid & 1;
        const int cbase = parity * 32;
        const int n = n0 + slot;
        const float4* mrow = (const float4*)(m + ((size_t)n * NRES + r) * CIN) + parity * 8;
        float x[32];
        float s = 0.f, sq = 0.f;
#pragma unroll
        for (int k = 0; k < 8; k++) {
            float4 v4 = mrow[k];
            x[4 * k + 0] = v4.x; x[4 * k + 1] = v4.y;
            x[4 * k + 2] = v4.z; x[4 * k + 3] = v4.w;
            s  += v4.x + v4.y + v4.z + v4.w;
            sq += v4.x * v4.x + v4.y * v4.y + v4.z * v4.z + v4.w * v4.w;
        }
        s  += __shfl_xor_sync(0xffffffffu, s, 1);
        sq += __shfl_xor_sync(0xffffffffu, sq, 1);
        float mu = s * (1.f / CIN);
        float rs = rsqrtf(sq * (1.f / CIN) - mu * mu + 1e-5f);
#pragma unroll
        for (int c = 0; c < 32; c++) {
            x[c] = (x[c] - mu) * rs * lnw_s[cbase + c] + lnb_s[cbase + c];
            buf[(cbase + c) * 128 + slot] = x[c];
        }

        const float mv = mask[(size_t)n * NRES + r];
#pragma unroll
        for (int c = 0; c < 32; c++) {
            float v = mv * x[c];
#pragma unroll
            for (int o = 16; o >= 2; o >>= 1) v += __shfl_xor_sync(0xffffffffu, v, o);
            if (lane < 2) qred[warp][lane * 32 + c] = (lane == (tid & 1)) ? v
                : __shfl_sync(0xffffffffu, v, lane);   // lanes 0/1 hold their parity sums
        }
        // (the shuffle above is identity for lanes 0/1; keep simple: rewrite)
        float mm = parity ? 0.f : mv;
        float mt = wsum(mm);
        if (lane == 0) mred[warp] = mt;
    }
    __syncthreads();
    if (tid < CIN) {
        float s2 = 0.f;
#pragma unroll
        for (int w = 0; w < 8; w++) s2 += qred[w][tid];
        g_qpart[((size_t)r * 16 + by) * CIN + tid] = s2;
    }
    if (tid == 0) {
        float s2 = 0.f;
#pragma unroll
        for (int w = 0; w < 8; w++) s2 += mred[w];
        g_mpart[r * 16 + by] = s2;
    }

    // ---- Stage B: k/v projection GEMM [128 rows x 16 cols x 64 k] ----
    {
        const int rowgrp = tid >> 4;       // 0..15
        const int j      = tid & 15;       // output col (0..7 k, 8..15 v)
        const int rowbase = rowgrp * 8;

        ull acc[4];
#pragma unroll
        for (int rp = 0; rp < 4; rp++) acc[rp] = 0ull;

#pragma unroll 8
        for (int k = 0; k < CIN; k++) {
            ulonglong2 x0 = *(const ulonglong2*)(buf + k * 128 + rowbase);
            ulonglong2 x1 = *(const ulonglong2*)(buf + k * 128 + rowbase + 4);
            ull wd = dup2(wkv_s[k * 16 + j]);
            acc[0] = fma2(x0.x, wd, acc[0]);
            acc[1] = fma2(x0.y, wd, acc[1]);
            acc[2] = fma2(x1.x, wd, acc[2]);
            acc[3] = fma2(x1.y, wd, acc[3]);
        }
#pragma unroll
        for (int rp = 0; rp < 4; rp++) {
            float2 t = unpk(acc[rp]);
            const int row = rowbase + 2 * rp;
            kv_s[row * 16 + j]       = t.x;
            kv_s[(row + 1) * 16 + j] = t.y;
        }
    }
    __syncthreads();

    // ---- coalesced kv store ----
    {
        const int n = tid >> 1, half = tid & 1;
        const float4* src = (const float4*)(kv_s + n * 16 + half * 8);
        float4 a = src[0], b = src[1];
        float* dst = (half ? g_v : g_k) + ((size_t)r * NSEQ + n0 + n) * NC;
        ((float4*)dst)[0] = a;
        ((float4*)dst)[1] = b;
    }
}

// =====================================================================
// Pass 2: per column r — q projection, logits, softmax, o accumulation.
// (R3 structure; now reduces the 16 q-sum partials)
// =====================================================================
__global__ void __launch_bounds__(512) pass2_kernel(
    const float* __restrict__ mask, const float* __restrict__ wq)
{
    const int r = blockIdx.x;
    const int tid = threadIdx.x;
    const int lane = tid & 31, warp = tid >> 5;
    const int slot = tid >> 1, hp = tid & 1;

    __shared__ float qpre[CIN];
    __shared__ float qh[CIN];
    __shared__ float msum_s;
    __shared__ float redm[16][NH];
    __shared__ float reds[16][NH];
    __shared__ float hmax_s[NH], hsum_s[NH];
    __shared__ float ored[16][CIN];

    if (tid < CIN) {
        float s = 0.f;
#pragma unroll
        for (int p = 0; p < 16; p++) s += g_qpart[((size_t)r * 16 + p) * CIN + tid];
        qpre[tid] = s;
    }
    if (tid == 64) {
        float s = 0.f;
#pragma unroll
        for (int p = 0; p < 16; p++) s += g_mpart[r * 16 + p];
        msum_s = s;
    }
    __syncthreads();
    if (tid < CIN) {
        float a = 0.f;
#pragma unroll
        for (int c = 0; c < CIN; c++) a += qpre[c] * wq[c * CIN + tid];
        qh[tid] = a * 0.3535533905932738f / (msum_s + 1e-10f);
    }
    __syncthreads();

    float l[8][4];
    float hmax[4];
#pragma unroll
    for (int h = 0; h < 4; h++) hmax[h] = -3.4e38f;

#pragma unroll
    for (int i = 0; i < 8; i++) {
        int n = i * 256 + slot;
        const float4* kp = (const float4*)(g_k + ((size_t)r * NSEQ + n) * NC);
        float4 k0 = kp[0], k1 = kp[1];
        float bias = (mask[(size_t)n * NRES + r] - 1.f) * 1000000000.0f;
#pragma unroll
        for (int h = 0; h < 4; h++) {
            const float* q = qh + (hp * 4 + h) * NC;
            float a = q[0] * k0.x + q[1] * k0.y + q[2] * k0.z + q[3] * k0.w
                    + q[4] * k1.x + q[5] * k1.y + q[6] * k1.z + q[7] * k1.w;
            a += bias;
            l[i][h] = a;
            hmax[h] = fmaxf(hmax[h], a);
        }
    }
#pragma unroll
    for (int h = 0; h < 4; h++) {
        float v = hmax[h];
#pragma unroll
        for (int o = 16; o >= 2; o >>= 1) v = fmaxf(v, __shfl_xor_sync(0xffffffffu, v, o));
        hmax[h] = v;
    }
    if (lane < 2) {
#pragma unroll
        for (int h = 0; h < 4; h++) redm[warp][lane * 4 + h] = hmax[h];
    }
    __syncthreads();
    if (tid < NH) {
        float v = -3.4e38f;
#pragma unroll
        for (int w = 0; w < 16; w++) v = fmaxf(v, redm[w][tid]);
        hmax_s[tid] = v;
    }
    __syncthreads();

    float hsum[4];
#pragma unroll
    for (int h = 0; h < 4; h++) hsum[h] = 0.f;
    float oacc[32];
#pragma unroll
    for (int j = 0; j < 32; j++) oacc[j] = 0.f;

#pragma unroll
    for (int i = 0; i < 8; i++) {
        int n = i * 256 + slot;
        const float4* vp = (const float4*)(g_v + ((size_t)r * NSEQ + n) * NC);
        float4 v0 = vp[0], v1 = vp[1];
#pragma unroll
        for (int h = 0; h < 4; h++) {
            float p = __expf(l[i][h] - hmax_s[hp * 4 + h]);
            hsum[h] += p;
            oacc[h * 8 + 0] += p * v0.x; oacc[h * 8 + 1] += p * v0.y;
            oacc[h * 8 + 2] += p * v0.z; oacc[h * 8 + 3] += p * v0.w;
            oacc[h * 8 + 4] += p * v1.x; oacc[h * 8 + 5] += p * v1.y;
            oacc[h * 8 + 6] += p * v1.z; oacc[h * 8 + 7] += p * v1.w;
        }
    }
#pragma unroll
    for (int h = 0; h < 4; h++) {
        float v = hsum[h];
#pragma unroll
        for (int o = 16; o >= 2; o >>= 1) v += __shfl_xor_sync(0xffffffffu, v, o);
        hsum[h] = v;
    }
#pragma unroll
    for (int j = 0; j < 32; j++) {
        float v = oacc[j];
#pragma unroll
        for (int o = 16; o >= 2; o >>= 1) v += __shfl_xor_sync(0xffffffffu, v, o);
        oacc[j] = v;
    }
    if (lane < 2) {
#pragma unroll
        for (int h = 0; h < 4; h++) reds[warp][lane * 4 + h] = hsum[h];
#pragma unroll
        for (int j = 0; j < 32; j++) ored[warp][lane * 32 + j] = oacc[j];
    }
    __syncthreads();
    if (tid < NH) {
        float v = 0.f;
#pragma unroll
        for (int w = 0; w < 16; w++) v += reds[w][tid];
        hsum_s[tid] = v;
    }
    __syncthreads();
    if (tid < CIN) {
        float s2 = 0.f;
#pragma unroll
        for (int w = 0; w < 16; w++) s2 += ored[w][tid];
        g_o[r * CIN + tid] = s2 / hsum_s[tid >> 3];
    }
}

// =====================================================================
// Pass 3 v4 (hot): block = (r, 128 n-rows), 2 CTAs/SM (65 KB smem).
// Thread tile 8 rows x 4 cols x 64 k; plain (non-dup) weights in smem,
// dup movs in-loop. Y row-swizzled by colgrp to keep epilogue-store
// conflicts low. Epilogue 2 stores directly to global.
// =====================================================================
#define P3_SMEM_FLOATS (8192 /*buf*/ + 4096 /*wg*/ + 4096 /*wo*/ + 320)
#define P3_SMEM_BYTES  (P3_SMEM_FLOATS * 4)

__global__ void __launch_bounds__(256, 2) pass3_kernel(
    const float* __restrict__ m,
    const float* __restrict__ lnw, const float* __restrict__ lnb,
    const float* __restrict__ wg, const float* __restrict__ bg,
    const float* __restrict__ wo, const float* __restrict__ bo,
    float* __restrict__ out)
{
    extern __shared__ __align__(16) float sm[];
    float* buf  = sm;                 // 8192 floats: X[k][128] then Y (swizzled)
    float* wg_s = sm + 8192;          // 4096
    float* wo_s = sm + 12288;         // 4096
    float* o_s  = sm + 16384;
    float* bg_s = o_s + 64;
    float* bo_s = bg_s + 64;
    float* lnw_s = bo_s + 64;
    float* lnb_s = lnw_s + 64;

    const int r   = blockIdx.x;
    const int tid = threadIdx.x;
    const int n0  = blockIdx.y * 128;

    for (int i = tid; i < CIN * CIN; i += 256) { wg_s[i] = wg[i]; wo_s[i] = wo[i]; }
    if (tid < CIN) {
        o_s[tid]  = g_o[r * CIN + tid];
        bg_s[tid] = bg[tid]; bo_s[tid] = bo[tid];
        lnw_s[tid] = lnw[tid]; lnb_s[tid] = lnb[tid];
    }
    __syncthreads();

    // ---- Stage A: layernorm (2 threads/row) -> buf[k][row] ----
    {
        const int slot = tid >> 1, parity = tid & 1;
        const int cbase = parity * 32;
        const int n = n0 + slot;
        const float4* mrow = (const float4*)(m + ((size_t)n * NRES + r) * CIN) + parity * 8;
        float x[32];
        float s = 0.f, sq = 0.f;
#pragma unroll
        for (int k = 0; k < 8; k++) {
            float4 v4 = mrow[k];
            x[4 * k + 0] = v4.x; x[4 * k + 1] = v4.y;
            x[4 * k + 2] = v4.z; x[4 * k + 3] = v4.w;
            s  += v4.x + v4.y + v4.z + v4.w;
            sq += v4.x * v4.x + v4.y * v4.y + v4.z * v4.z + v4.w * v4.w;
        }
        s  += __shfl_xor_sync(0xffffffffu, s, 1);
        sq += __shfl_xor_sync(0xffffffffu, sq, 1);
        float mu = s * (1.f / CIN);
        float rs = rsqrtf(sq * (1.f / CIN) - mu * mu + 1e-5f);
#pragma unroll
        for (int c = 0; c < 32; c++)
            buf[(cbase + c) * 128 + slot] =
                (x[c] - mu) * rs * lnw_s[cbase + c] + lnb_s[cbase + c];
    }
    __syncthreads();

    const int rowgrp = tid >> 4;          // 0..15
    const int colgrp = tid & 15;          // 0..15
    const int rowbase = rowgrp * 8;
    const int colbase = colgrp * 4;
    const int sc = (colgrp & 7) << 2;     // Y row swizzle for this thread's cols

    ull acc[4][4];

    // ================= GEMM 1: gpre = X @ Wg =================
#pragma unroll
    for (int rp = 0; rp < 4; rp++)
#pragma unroll
        for (int c = 0; c < 4; c++) acc[rp][c] = 0ull;

#pragma unroll 4
    for (int k = 0; k < CIN; k++) {
        ulonglong2 x0 = *(const ulonglong2*)(buf + k * 128 + rowbase);
        ulonglong2 x1 = *(const ulonglong2*)(buf + k * 128 + rowbase + 4);
        float4 w = *(const float4*)(wg_s + k * CIN + colbase);
        ull wd0 = dup2(w.x), wd1 = dup2(w.y), wd2 = dup2(w.z), wd3 = dup2(w.w);
        acc[0][0] = fma2(x0.x, wd0, acc[0][0]); acc[0][1] = fma2(x0.x, wd1, acc[0][1]);
        acc[0][2] = fma2(x0.x, wd2, acc[0][2]); acc[0][3] = fma2(x0.x, wd3, acc[0][3]);
        acc[1][0] = fma2(x0.y, wd0, acc[1][0]); acc[1][1] = fma2(x0.y, wd1, acc[1][1]);
        acc[1][2] = fma2(x0.y, wd2, acc[1][2]); acc[1][3] = fma2(x0.y, wd3, acc[1][3]);
        acc[2][0] = fma2(x1.x, wd0, acc[2][0]); acc[2][1] = fma2(x1.x, wd1, acc[2][1]);
        acc[2][2] = fma2(x1.x, wd2, acc[2][2]); acc[2][3] = fma2(x1.x, wd3, acc[2][3]);
        acc[3][0] = fma2(x1.y, wd0, acc[3][0]); acc[3][1] = fma2(x1.y, wd1, acc[3][1]);
        acc[3][2] = fma2(x1.y, wd2, acc[3][2]); acc[3][3] = fma2(x1.y, wd3, acc[3][3]);
    }
    __syncthreads();   // all X reads done before Y overwrites buf

    // ---- epilogue 1: y = o * sigmoid(gpre + bg) -> buf[col][row ^ sc] ----
#pragma unroll
    for (int c = 0; c < 4; c++) {
        const int col = colbase + c;
        const float bgc = bg_s[col];
        const float oc  = o_s[col];
#pragma unroll
        for (int rp = 0; rp < 4; rp++) {
            float2 t = unpk(acc[rp][c]);
            float y0 = oc / (1.f + __expf(-(t.x + bgc)));
            float y1 = oc / (1.f + __expf(-(t.y + bgc)));
            const int row = rowbase + 2 * rp;
            *(ull*)(buf + col * 128 + (row ^ sc)) = pack2(y0, y1);
        }
    }
    __syncthreads();

    // ================= GEMM 2: out = Y @ Wo =================
#pragma unroll
    for (int rp = 0; rp < 4; rp++)
#pragma unroll
        for (int c = 0; c < 4; c++) acc[rp][c] = 0ull;

#pragma unroll 4
    for (int k = 0; k < CIN; k++) {
        const int sck = ((k >> 2) & 7) << 2;
        ulonglong2 x0 = *(const ulonglong2*)(buf + k * 128 + (rowbase ^ sck));
        ulonglong2 x1 = *(const ulonglong2*)(buf + k * 128 + ((rowbase + 4) ^ sck));
        float4 w = *(const float4*)(wo_s + k * CIN + colbase);
        ull wd0 = dup2(w.x), wd1 = dup2(w.y), wd2 = dup2(w.z), wd3 = dup2(w.w);
        acc[0][0] = fma2(x0.x, wd0, acc[0][0]); acc[0][1] = fma2(x0.x, wd1, acc[0][1]);
        acc[0][2] = fma2(x0.x, wd2, acc[0][2]); acc[0][3] = fma2(x0.x, wd3, acc[0][3]);
        acc[1][0] = fma2(x0.y, wd0, acc[1][0]); acc[1][1] = fma2(x0.y, wd1, acc[1][1]);
        acc[1][2] = fma2(x0.y, wd2, acc[1][2]); acc[1][3] = fma2(x0.y, wd3, acc[1][3]);
        acc[2][0] = fma2(x1.x, wd0, acc[2][0]); acc[2][1] = fma2(x1.x, wd1, acc[2][1]);
        acc[2][2] = fma2(x1.x, wd2, acc[2][2]); acc[2][3] = fma2(x1.x, wd3, acc[2][3]);
        acc[3][0] = fma2(x1.y, wd0, acc[3][0]); acc[3][1] = fma2(x1.y, wd1, acc[3][1]);
        acc[3][2] = fma2(x1.y, wd2, acc[3][2]); acc[3][3] = fma2(x1.y, wd3, acc[3][3]);
    }

    // ---- epilogue 2: add bias, store directly to global ----
    {
        const float b0 = bo_s[colbase + 0], b1 = bo_s[colbase + 1];
        const float b2 = bo_s[colbase + 2], b3 = bo_s[colbase + 3];
#pragma unroll
        for (int rp = 0; rp < 4; rp++) {
            float2 t0 = unpk(acc[rp][0]), t1 = unpk(acc[rp][1]);
            float2 t2 = unpk(acc[rp][2]), t3 = unpk(acc[rp][3]);
            const int row = rowbase + 2 * rp;
            float4 v;
            v.x = t0.x + b0; v.y = t1.x + b1; v.z = t2.x + b2; v.w = t3.x + b3;
            *(float4*)(out + ((size_t)(n0 + row) * NRES + r) * CIN + colbase) = v;
            v.x = t0.y + b0; v.y = t1.y + b1; v.z = t2.y + b2; v.w = t3.y + b3;
            *(float4*)(out + ((size_t)(n0 + row + 1) * NRES + r) * CIN + colbase) = v;
        }
    }
}

extern "C" void kernel_launch(void* const* d_in, const int* in_sizes, int n_in,
                              void* d_out, int out_size) {
    const float* m    = (const float*)d_in[0];
    const float* mask = (const float*)d_in[1];
    const float* lnw  = (const float*)d_in[2];
    const float* lnb  = (const float*)d_in[3];
    const float* wq   = (const float*)d_in[4];
    const float* wk   = (const float*)d_in[5];
    const float* wv   = (const float*)d_in[6];
    const float* wg   = (const float*)d_in[7];
    const float* bg   = (const float*)d_in[8];
    const float* wo   = (const float*)d_in[9];
    const float* bo   = (const float*)d_in[10];
    float* out = (float*)d_out;

    cudaFuncSetAttribute(pass3_kernel,
                         cudaFuncAttributeMaxDynamicSharedMemorySize, P3_SMEM_BYTES);

    pass1_kernel<<<dim3(NRES, 16), 256>>>(m, mask, lnw, lnb, wk, wv);
    pass2_kernel<<<NRES, 512>>>(mask, wq);
    pass3_kernel<<<dim3(NRES, 16), 256, P3_SMEM_BYTES>>>(
        m, lnw, lnb, wg, bg, wo, bo, out);
}

// round 7
// speedup vs baseline: 2.1559x; 1.0048x over previous
#include <cuda_runtime.h>

typedef unsigned long long ull;

#define NSEQ 2048
#define NRES 512
#define CIN  64
#define NH   8
#define NC   8

// ---------------- scratch (device globals: allocation-free) ----------------
__device__ __align__(16) float g_k[(size_t)NRES * NSEQ * NC];      // 32 MB
__device__ __align__(16) float g_v[(size_t)NRES * NSEQ * NC];      // 32 MB
__device__ __align__(16) float g_xt[(size_t)NRES * CIN * NSEQ];    // 256 MB  X^T [r][k][n]
__device__ __align__(16) float g_qpart[NRES * 16 * CIN];
__device__ __align__(16) float g_mpart[NRES * 16];
__device__ __align__(16) float g_o[NRES * CIN];

// ---------------- packed f32x2 helpers ----------------
__device__ __forceinline__ ull fma2(ull a, ull b, ull c) {
    ull d;
    asm("fma.rn.f32x2 %0, %1, %2, %3;" : "=l"(d) : "l"(a), "l"(b), "l"(c));
    return d;
}
__device__ __forceinline__ ull dup2(float x) {
    ull d; unsigned xi = __float_as_uint(x);
    asm("mov.b64 %0, {%1, %1};" : "=l"(d) : "r"(xi));
    return d;
}
__device__ __forceinline__ ull pack2(float lo, float hi) {
    ull d;
    asm("mov.b64 %0, {%1, %2};" : "=l"(d) : "r"(__float_as_uint(lo)), "r"(__float_as_uint(hi)));
    return d;
}
__device__ __forceinline__ float2 unpk(ull a) {
    unsigned lo, hi;
    asm("mov.b64 {%0, %1}, %2;" : "=r"(lo), "=r"(hi) : "l"(a));
    return make_float2(__uint_as_float(lo), __uint_as_float(hi));
}
__device__ __forceinline__ float wsum(float v) {
#pragma unroll
    for (int o = 16; o; o >>= 1) v += __shfl_xor_sync(0xffffffffu, v, o);
    return v;
}

// =====================================================================
// Pass 1 v3: block = (r, 128 n-rows).
//  A0: coalesced LDG of m tile -> raw[row][68] (smem staging).
//  A1: LN (2 thr/row) from raw -> buf X[k][row]; masked q-sum partials.
//  B:  smem GEMM for k/v; kv_s staging (aliases raw).
//  C:  coalesced kv store + coalesced X^T store to g_xt.
// =====================================================================
#define P1_SMEM_FLOATS (8192 /*buf*/ + 8704 /*raw|kv_s*/ + 1024 /*wkv*/ + 128 /*ln*/ + 512 /*qred*/ + 8 /*mred*/)
#define P1_SMEM_BYTES  (P1_SMEM_FLOATS * 4)

__global__ void __launch_bounds__(256, 2) pass1_kernel(
    const float* __restrict__ m, const float* __restrict__ mask,
    const float* __restrict__ lnw, const float* __restrict__ lnb,
    const float* __restrict__ wk, const float* __restrict__ wv)
{
    extern __shared__ __align__(16) float sm1[];
    float* buf   = sm1;                    // 8192: X[k][128]
    float* raw   = sm1 + 8192;             // 8704: m tile [row][68]  (aliased by kv_s)
    float* kv_s  = sm1 + 8192;             // 2048: kv staging (after raw is dead)
    float* wkv_s = sm1 + 16896;            // 1024
    float* lnw_s = sm1 + 17920;            // 64
    float* lnb_s = sm1 + 17984;            // 64
    float* qred  = sm1 + 18048;            // 8 warps x 64
    float* mred  = sm1 + 18560;            // 8

    const int r   = blockIdx.x;
    const int by  = blockIdx.y;
    const int n0  = by * 128;
    const int tid = threadIdx.x;
    const int lane = tid & 31, warp = tid >> 5;

    for (int i = tid; i < CIN * 16; i += 256) {
        int c = i >> 4, j = i & 15;
        wkv_s[i] = (j < 8) ? wk[c * 8 + j] : wv[c * 8 + (j - 8)];
    }
    if (tid < CIN) { lnw_s[tid] = lnw[tid]; lnb_s[tid] = lnb[tid]; }
    __syncthreads();

    // ---- A0: coalesced m tile load -> raw ----
    for (int i = tid; i < 2048; i += 256) {
        const int row = i >> 4, k4 = i & 15;
        float4 v = *(const float4*)(m + ((size_t)(n0 + row) * NRES + r) * CIN + k4 * 4);
        *(float4*)(raw + row * 68 + k4 * 4) = v;
    }
    __syncthreads();

    // ---- A1: layernorm + masked q-sum partial ----
    {
        const int slot = tid >> 1, parity = tid & 1;
        const int cbase = parity * 32;
        const float4* rr = (const float4*)(raw + slot * 68 + cbase);
        float x[32];
        float s = 0.f, sq = 0.f;
#pragma unroll
        for (int k = 0; k < 8; k++) {
            float4 v4 = rr[k];
            x[4 * k + 0] = v4.x; x[4 * k + 1] = v4.y;
            x[4 * k + 2] = v4.z; x[4 * k + 3] = v4.w;
            s  += v4.x + v4.y + v4.z + v4.w;
            sq += v4.x * v4.x + v4.y * v4.y + v4.z * v4.z + v4.w * v4.w;
        }
        s  += __shfl_xor_sync(0xffffffffu, s, 1);
        sq += __shfl_xor_sync(0xffffffffu, sq, 1);
        float mu = s * (1.f / CIN);
        float rs = rsqrtf(sq * (1.f / CIN) - mu * mu + 1e-5f);
#pragma unroll
        for (int c = 0; c < 32; c++) {
            x[c] = (x[c] - mu) * rs * lnw_s[cbase + c] + lnb_s[cbase + c];
            buf[(cbase + c) * 128 + slot] = x[c];
        }

        const float mv = mask[(size_t)(n0 + slot) * NRES + r];
#pragma unroll
        for (int c = 0; c < 32; c++) {
            float v = mv * x[c];
#pragma unroll
            for (int o = 16; o >= 2; o >>= 1) v += __shfl_xor_sync(0xffffffffu, v, o);
            if (lane < 2) qred[warp * 64 + lane * 32 + c] = v;
        }
        float mm = parity ? 0.f : mv;
        float mt = wsum(mm);
        if (lane == 0) mred[warp] = mt;
    }
    __syncthreads();   // raw dead from here; kv_s may reuse it

    // ---- partial q/m sums to global ----
    if (tid < CIN) {
        float s2 = 0.f;
#pragma unroll
        for (int w = 0; w < 8; w++) s2 += qred[w * 64 + tid];
        g_qpart[((size_t)r * 16 + by) * CIN + tid] = s2;
    }
    if (tid == 64) {
        float s2 = 0.f;
#pragma unroll
        for (int w = 0; w < 8; w++) s2 += mred[w];
        g_mpart[r * 16 + by] = s2;
    }

    // ---- B: k/v projection GEMM [128 rows x 16 cols x 64 k] ----
    {
        const int rowgrp = tid >> 4;
        const int j      = tid & 15;
        const int rowbase = rowgrp * 8;

        ull acc[4];
#pragma unroll
        for (int rp = 0; rp < 4; rp++) acc[rp] = 0ull;

#pragma unroll 8
        for (int k = 0; k < CIN; k++) {
            ulonglong2 x0 = *(const ulonglong2*)(buf + k * 128 + rowbase);
            ulonglong2 x1 = *(const ulonglong2*)(buf + k * 128 + rowbase + 4);
            ull wd = dup2(wkv_s[k * 16 + j]);
            acc[0] = fma2(x0.x, wd, acc[0]);
            acc[1] = fma2(x0.y, wd, acc[1]);
            acc[2] = fma2(x1.x, wd, acc[2]);
            acc[3] = fma2(x1.y, wd, acc[3]);
        }
#pragma unroll
        for (int rp = 0; rp < 4; rp++) {
            float2 t = unpk(acc[rp]);
            const int row = rowbase + 2 * rp;
            kv_s[row * 16 + j]       = t.x;
            kv_s[(row + 1) * 16 + j] = t.y;
        }
    }
    __syncthreads();

    // ---- C: coalesced kv store + X^T store ----
    {
        const int n = tid >> 1, half = tid & 1;
        const float4* src = (const float4*)(kv_s + n * 16 + half * 8);
        float4 a = src[0], b = src[1];
        float* dst = (half ? g_v : g_k) + ((size_t)r * NSEQ + n0 + n) * NC;
        ((float4*)dst)[0] = a;
        ((float4*)dst)[1] = b;
    }
    for (int i = tid; i < 2048; i += 256) {
        const int k = i >> 5, rc = i & 31;
        float4 v = ((const float4*)buf)[k * 32 + rc];
        ((float4*)(g_xt + ((size_t)r * CIN + k) * NSEQ + n0))[rc] = v;
    }
}

// =====================================================================
// Pass 2: per column r — q projection, logits, softmax, o accumulation.
// (unchanged; reduces the 16 q-sum partials)
// =====================================================================
__global__ void __launch_bounds__(512) pass2_kernel(
    const float* __restrict__ mask, const float* __restrict__ wq)
{
    const int r = blockIdx.x;
    const int tid = threadIdx.x;
    const int lane = tid & 31, warp = tid >> 5;
    const int slot = tid >> 1, hp = tid & 1;

    __shared__ float qpre[CIN];
    __shared__ float qh[CIN];
    __shared__ float msum_s;
    __shared__ float redm[16][NH];
    __shared__ float reds[16][NH];
    __shared__ float hmax_s[NH], hsum_s[NH];
    __shared__ float ored[16][CIN];

    if (tid < CIN) {
        float s = 0.f;
#pragma unroll
        for (int p = 0; p < 16; p++) s += g_qpart[((size_t)r * 16 + p) * CIN + tid];
        qpre[tid] = s;
    }
    if (tid == 64) {
        float s = 0.f;
#pragma unroll
        for (int p = 0; p < 16; p++) s += g_mpart[r * 16 + p];
        msum_s = s;
    }
    __syncthreads();
    if (tid < CIN) {
        float a = 0.f;
#pragma unroll
        for (int c = 0; c < CIN; c++) a += qpre[c] * wq[c * CIN + tid];
        qh[tid] = a * 0.3535533905932738f / (msum_s + 1e-10f);
    }
    __syncthreads();

    float l[8][4];
    float hmax[4];
#pragma unroll
    for (int h = 0; h < 4; h++) hmax[h] = -3.4e38f;

#pragma unroll
    for (int i = 0; i < 8; i++) {
        int n = i * 256 + slot;
        const float4* kp = (const float4*)(g_k + ((size_t)r * NSEQ + n) * NC);
        float4 k0 = kp[0], k1 = kp[1];
        float bias = (mask[(size_t)n * NRES + r] - 1.f) * 1000000000.0f;
#pragma unroll
        for (int h = 0; h < 4; h++) {
            const float* q = qh + (hp * 4 + h) * NC;
            float a = q[0] * k0.x + q[1] * k0.y + q[2] * k0.z + q[3] * k0.w
                    + q[4] * k1.x + q[5] * k1.y + q[6] * k1.z + q[7] * k1.w;
            a += bias;
            l[i][h] = a;
            hmax[h] = fmaxf(hmax[h], a);
        }
    }
#pragma unroll
    for (int h = 0; h < 4; h++) {
        float v = hmax[h];
#pragma unroll
        for (int o = 16; o >= 2; o >>= 1) v = fmaxf(v, __shfl_xor_sync(0xffffffffu, v, o));
        hmax[h] = v;
    }
    if (lane < 2) {
#pragma unroll
        for (int h = 0; h < 4; h++) redm[warp][lane * 4 + h] = hmax[h];
    }
    __syncthreads();
    if (tid < NH) {
        float v = -3.4e38f;
#pragma unroll
        for (int w = 0; w < 16; w++) v = fmaxf(v, redm[w][tid]);
        hmax_s[tid] = v;
    }
    __syncthreads();

    float hsum[4];
#pragma unroll
    for (int h = 0; h < 4; h++) hsum[h] = 0.f;
    float oacc[32];
#pragma unroll
    for (int j = 0; j < 32; j++) oacc[j] = 0.f;

#pragma unroll
    for (int i = 0; i < 8; i++) {
        int n = i * 256 + slot;
        const float4* vp = (const float4*)(g_v + ((size_t)r * NSEQ + n) * NC);
        float4 v0 = vp[0], v1 = vp[1];
#pragma unroll
        for (int h = 0; h < 4; h++) {
            float p = __expf(l[i][h] - hmax_s[hp * 4 + h]);
            hsum[h] += p;
            oacc[h * 8 + 0] += p * v0.x; oacc[h * 8 + 1] += p * v0.y;
            oacc[h * 8 + 2] += p * v0.z; oacc[h * 8 + 3] += p * v0.w;
            oacc[h * 8 + 4] += p * v1.x; oacc[h * 8 + 5] += p * v1.y;
            oacc[h * 8 + 6] += p * v1.z; oacc[h * 8 + 7] += p * v1.w;
        }
    }
#pragma unroll
    for (int h = 0; h < 4; h++) {
        float v = hsum[h];
#pragma unroll
        for (int o = 16; o >= 2; o >>= 1) v += __shfl_xor_sync(0xffffffffu, v, o);
        hsum[h] = v;
    }
#pragma unroll
    for (int j = 0; j < 32; j++) {
        float v = oacc[j];
#pragma unroll
        for (int o = 16; o >= 2; o >>= 1) v += __shfl_xor_sync(0xffffffffu, v, o);
        oacc[j] = v;
    }
    if (lane < 2) {
#pragma unroll
        for (int h = 0; h < 4; h++) reds[warp][lane * 4 + h] = hsum[h];
#pragma unroll
        for (int j = 0; j < 32; j++) ored[warp][lane * 32 + j] = oacc[j];
    }
    __syncthreads();
    if (tid < NH) {
        float v = 0.f;
#pragma unroll
        for (int w = 0; w < 16; w++) v += reds[w][tid];
        hsum_s[tid] = v;
    }
    __syncthreads();
    if (tid < CIN) {
        float s2 = 0.f;
#pragma unroll
        for (int w = 0; w < 16; w++) s2 += ored[w][tid];
        g_o[r * CIN + tid] = s2 / hsum_s[tid >> 3];
    }
}

// =====================================================================
// Pass 3 v5 (hot): block = (r, 256 n-rows), 2 CTAs/SM (99 KB smem).
// No LN here — reads pre-normalized X^T from g_xt (coalesced copy).
// Thread tile 8 rows x 8 cols x 64 k; acc packed over row pairs.
// Y stored with (col>>3)<<2 row-XOR swizzle for GEMM2.
// =====================================================================
#define P3_SMEM_FLOATS (16384 /*buf*/ + 4096 /*wg*/ + 4096 /*wo*/ + 192)
#define P3_SMEM_BYTES  (P3_SMEM_FLOATS * 4)

__global__ void __launch_bounds__(256, 2) pass3_kernel(
    const float* __restrict__ wg, const float* __restrict__ bg,
    const float* __restrict__ wo, const float* __restrict__ bo,
    float* __restrict__ out)
{
    extern __shared__ __align__(16) float sm3[];
    float* buf  = sm3;                 // 16384: X[k][256] -> Y (swizzled)
    float* wg_s = sm3 + 16384;         // 4096
    float* wo_s = sm3 + 20480;         // 4096
    float* o_s  = sm3 + 24576;
    float* bg_s = o_s + 64;
    float* bo_s = bg_s + 64;

    const int r   = blockIdx.x;
    const int tid = threadIdx.x;
    const int n0  = blockIdx.y * 256;

    for (int i = tid; i < CIN * CIN; i += 256) { wg_s[i] = wg[i]; wo_s[i] = wo[i]; }
    if (tid < CIN) {
        o_s[tid]  = g_o[r * CIN + tid];
        bg_s[tid] = bg[tid]; bo_s[tid] = bo[tid];
    }

    // ---- Stage A: coalesced X^T tile copy: g_xt[r][k][n0..n0+256) -> buf ----
#pragma unroll
    for (int t = 0; t < 16; t++) {
        const int i = t * 256 + tid;
        const int k = i >> 6, rc = i & 63;
        float4 v = ((const float4*)(g_xt + ((size_t)r * CIN + k) * NSEQ + n0))[rc];
        ((float4*)buf)[k * 64 + rc] = v;
    }
    __syncthreads();

    const int rowgrp = tid >> 3;          // 0..31
    const int colgrp = tid & 7;           // 0..7
    const int rowbase = rowgrp * 8;
    const int colbase = colgrp * 8;
    const int sc = colgrp << 2;           // Y swizzle for this thread's cols

    ull acc[4][8];

    // ================= GEMM 1: gpre = X @ Wg =================
#pragma unroll
    for (int rp = 0; rp < 4; rp++)
#pragma unroll
        for (int c = 0; c < 8; c++) acc[rp][c] = 0ull;

#pragma unroll 2
    for (int k = 0; k < CIN; k++) {
        ulonglong2 x0 = *(const ulonglong2*)(buf + k * 256 + rowbase);
        ulonglong2 x1 = *(const ulonglong2*)(buf + k * 256 + rowbase + 4);
        float4 wa = *(const float4*)(wg_s + k * CIN + colbase);
        float4 wb = *(const float4*)(wg_s + k * CIN + colbase + 4);
        ull xs[4] = {x0.x, x0.y, x1.x, x1.y};
        ull wd[8] = {dup2(wa.x), dup2(wa.y), dup2(wa.z), dup2(wa.w),
                     dup2(wb.x), dup2(wb.y), dup2(wb.z), dup2(wb.w)};
#pragma unroll
        for (int rp = 0; rp < 4; rp++)
#pragma unroll
            for (int c = 0; c < 8; c++)
                acc[rp][c] = fma2(xs[rp], wd[c], acc[rp][c]);
    }
    __syncthreads();   // all X reads done before Y overwrites buf

    // ---- epilogue 1: y = o * sigmoid(gpre + bg) -> buf[col][row ^ sc] ----
#pragma unroll
    for (int c = 0; c < 8; c++) {
        const int col = colbase + c;
        const float bgc = bg_s[col];
        const float oc  = o_s[col];
#pragma unroll
        for (int rp = 0; rp < 4; rp++) {
            float2 t = unpk(acc[rp][c]);
            float y0 = oc / (1.f + __expf(-(t.x + bgc)));
            float y1 = oc / (1.f + __expf(-(t.y + bgc)));
            const int row = rowbase + 2 * rp;
            *(ull*)(buf + col * 256 + (row ^ sc)) = pack2(y0, y1);
        }
    }
    __syncthreads();

    // ================= GEMM 2: out = Y @ Wo =================
#pragma unroll
    for (int rp = 0; rp < 4; rp++)
#pragma unroll
        for (int c = 0; c < 8; c++) acc[rp][c] = 0ull;

#pragma unroll 2
    for (int k = 0; k < CIN; k++) {
        const int sck = ((k >> 3) & 7) << 2;
        ulonglong2 x0 = *(const ulonglong2*)(buf + k * 256 + (rowbase ^ sck));
        ulonglong2 x1 = *(const ulonglong2*)(buf + k * 256 + ((rowbase + 4) ^ sck));
        float4 wa = *(const float4*)(wo_s + k * CIN + colbase);
        float4 wb = *(const float4*)(wo_s + k * CIN + colbase + 4);
        ull xs[4] = {x0.x, x0.y, x1.x, x1.y};
        ull wd[8] = {dup2(wa.x), dup2(wa.y), dup2(wa.z), dup2(wa.w),
                     dup2(wb.x), dup2(wb.y), dup2(wb.z), dup2(wb.w)};
#pragma unroll
        for (int rp = 0; rp < 4; rp++)
#pragma unroll
            for (int c = 0; c < 8; c++)
                acc[rp][c] = fma2(xs[rp], wd[c], acc[rp][c]);
    }

    // ---- epilogue 2: add bias, store directly to global ----
    {
        float b[8];
#pragma unroll
        for (int c = 0; c < 8; c++) b[c] = bo_s[colbase + c];
#pragma unroll
        for (int rp = 0; rp < 4; rp++) {
            float2 t[8];
#pragma unroll
            for (int c = 0; c < 8; c++) t[c] = unpk(acc[rp][c]);
#pragma unroll
            for (int e = 0; e < 2; e++) {
                const int row = rowbase + 2 * rp + e;
                float4 v0, v1;
                v0.x = (e ? t[0].y : t[0].x) + b[0];
                v0.y = (e ? t[1].y : t[1].x) + b[1];
                v0.z = (e ? t[2].y : t[2].x) + b[2];
                v0.w = (e ? t[3].y : t[3].x) + b[3];
                v1.x = (e ? t[4].y : t[4].x) + b[4];
                v1.y = (e ? t[5].y : t[5].x) + b[5];
                v1.z = (e ? t[6].y : t[6].x) + b[6];
                v1.w = (e ? t[7].y : t[7].x) + b[7];
                float4* dst = (float4*)(out + ((size_t)(n0 + row) * NRES + r) * CIN + colbase);
                dst[0] = v0;
                dst[1] = v1;
            }
        }
    }
}

extern "C" void kernel_launch(void* const* d_in, const int* in_sizes, int n_in,
                              void* d_out, int out_size) {
    const float* m    = (const float*)d_in[0];
    const float* mask = (const float*)d_in[1];
    const float* lnw  = (const float*)d_in[2];
    const float* lnb  = (const float*)d_in[3];
    const float* wq   = (const float*)d_in[4];
    const float* wk   = (const float*)d_in[5];
    const float* wv   = (const float*)d_in[6];
    const float* wg   = (const float*)d_in[7];
    const float* bg   = (const float*)d_in[8];
    const float* wo   = (const float*)d_in[9];
    const float* bo   = (const float*)d_in[10];
    float* out = (float*)d_out;

    cudaFuncSetAttribute(pass1_kernel,
                         cudaFuncAttributeMaxDynamicSharedMemorySize, P1_SMEM_BYTES);
    cudaFuncSetAttribute(pass3_kernel,
                         cudaFuncAttributeMaxDynamicSharedMemorySize, P3_SMEM_BYTES);

    pass1_kernel<<<dim3(NRES, 16), 256, P1_SMEM_BYTES>>>(m, mask, lnw, lnb, wk, wv);
    pass2_kernel<<<NRES, 512>>>(mask, wq);
    pass3_kernel<<<dim3(NRES, 8), 256, P3_SMEM_BYTES>>>(wg, bg, wo, bo, out);
}

// round 8
// speedup vs baseline: 2.5244x; 1.1710x over previous
#include <cuda_runtime.h>

typedef unsigned long long ull;

#define NSEQ 2048
#define NRES 512
#define CIN  64
#define NH   8
#define NC   8

// ---------------- scratch (device globals: allocation-free) ----------------
__device__ __align__(16) float g_k[(size_t)NRES * NSEQ * NC];      // 32 MB
__device__ __align__(16) float g_v[(size_t)NRES * NSEQ * NC];      // 32 MB
__device__ __align__(16) float g_xt[(size_t)NRES * CIN * NSEQ];    // 256 MB  X^T [r][k][n]
__device__ __align__(16) float g_qpart[NRES * 16 * CIN];
__device__ __align__(16) float g_mpart[NRES * 16];
__device__ __align__(16) float g_o[NRES * CIN];

// ---------------- packed f32x2 helpers ----------------
__device__ __forceinline__ ull fma2(ull a, ull b, ull c) {
    ull d;
    asm("fma.rn.f32x2 %0, %1, %2, %3;" : "=l"(d) : "l"(a), "l"(b), "l"(c));
    return d;
}
__device__ __forceinline__ ull dup2(float x) {
    ull d; unsigned xi = __float_as_uint(x);
    asm("mov.b64 %0, {%1, %1};" : "=l"(d) : "r"(xi));
    return d;
}
__device__ __forceinline__ ull pack2(float lo, float hi) {
    ull d;
    asm("mov.b64 %0, {%1, %2};" : "=l"(d) : "r"(__float_as_uint(lo)), "r"(__float_as_uint(hi)));
    return d;
}
__device__ __forceinline__ float2 unpk(ull a) {
    unsigned lo, hi;
    asm("mov.b64 {%0, %1}, %2;" : "=r"(lo), "=r"(hi) : "l"(a));
    return make_float2(__uint_as_float(lo), __uint_as_float(hi));
}
__device__ __forceinline__ float wsum(float v) {
#pragma unroll
    for (int o = 16; o; o >>= 1) v += __shfl_xor_sync(0xffffffffu, v, o);
    return v;
}

// =====================================================================
// Pass 1 v4: block = (r, 128 n-rows), 3 CTAs/SM (57 KB smem).
// Two 64-row staging phases (raw halved), LN with 4 threads/row,
// g_xt store issued before kv GEMM to overlap its latency.
// =====================================================================
#define P1_SMEM_FLOATS (8192 /*buf*/ + 4352 /*raw|kv_s*/ + 1024 /*wkv*/ + 128 /*ln*/ + 512 /*qred*/ + 8 /*mred*/)
#define P1_SMEM_BYTES  (P1_SMEM_FLOATS * 4)

__global__ void __launch_bounds__(256, 3) pass1_kernel(
    const float* __restrict__ m, const float* __restrict__ mask,
    const float* __restrict__ lnw, const float* __restrict__ lnb,
    const float* __restrict__ wk, const float* __restrict__ wv)
{
    extern __shared__ __align__(16) float sm1[];
    float* buf   = sm1;                    // 8192: X[k][128]
    float* raw   = sm1 + 8192;             // 4352: m half-tile [row][68] (aliased by kv_s)
    float* kv_s  = sm1 + 8192;             // 2048: kv staging (after raw is dead)
    float* wkv_s = sm1 + 12544;            // 1024
    float* lnw_s = sm1 + 13568;            // 64
    float* lnb_s = sm1 + 13632;            // 64
    float* qred  = sm1 + 13696;            // 8 warps x 64
    float* mred  = sm1 + 14208;            // 8

    const int r   = blockIdx.x;
    const int by  = blockIdx.y;
    const int n0  = by * 128;
    const int tid = threadIdx.x;
    const int lane = tid & 31, warp = tid >> 5;
    const int slot = tid >> 2, quarter = tid & 3;   // LN: 4 threads/row
    const int cb   = quarter * 16;

    for (int i = tid; i < CIN * 16; i += 256) {
        int c = i >> 4, j = i & 15;
        wkv_s[i] = (j < 8) ? wk[c * 8 + j] : wv[c * 8 + (j - 8)];
    }
    if (tid < CIN) { lnw_s[tid] = lnw[tid]; lnb_s[tid] = lnb[tid]; }
    __syncthreads();

    float qacc[16];
#pragma unroll
    for (int c = 0; c < 16; c++) qacc[c] = 0.f;
    float macc = 0.f;

#pragma unroll
    for (int half = 0; half < 2; half++) {
        // ---- A0: coalesced 64-row m half-tile -> raw ----
        for (int i = tid; i < 1024; i += 256) {
            const int row = i >> 4, k4 = i & 15;
            float4 v = *(const float4*)(m + ((size_t)(n0 + half * 64 + row) * NRES + r) * CIN + k4 * 4);
            *(float4*)(raw + row * 68 + k4 * 4) = v;
        }
        __syncthreads();

        // ---- A1: layernorm (4 thr/row, 16 channels each) ----
        {
            const float4* rr = (const float4*)(raw + slot * 68 + cb);
            float x[16];
            float s = 0.f, sq = 0.f;
#pragma unroll
            for (int k = 0; k < 4; k++) {
                float4 v4 = rr[k];
                x[4 * k + 0] = v4.x; x[4 * k + 1] = v4.y;
                x[4 * k + 2] = v4.z; x[4 * k + 3] = v4.w;
                s  += v4.x + v4.y + v4.z + v4.w;
                sq += v4.x * v4.x + v4.y * v4.y + v4.z * v4.z + v4.w * v4.w;
            }
            s  += __shfl_xor_sync(0xffffffffu, s, 1);
            sq += __shfl_xor_sync(0xffffffffu, sq, 1);
            s  += __shfl_xor_sync(0xffffffffu, s, 2);
            sq += __shfl_xor_sync(0xffffffffu, sq, 2);
            float mu = s * (1.f / CIN);
            float rs = rsqrtf(sq * (1.f / CIN) - mu * mu + 1e-5f);
            const int row_g = half * 64 + slot;
#pragma unroll
            for (int c = 0; c < 16; c++) {
                x[c] = (x[c] - mu) * rs * lnw_s[cb + c] + lnb_s[cb + c];
                buf[(cb + c) * 128 + row_g] = x[c];
            }
            const float mv = mask[(size_t)(n0 + row_g) * NRES + r];
#pragma unroll
            for (int c = 0; c < 16; c++) qacc[c] += mv * x[c];
            if (quarter == 0) macc += mv;
        }
        __syncthreads();   // raw will be reloaded (or aliased) next
    }

    // ---- X^T store first (latency overlaps with the kv GEMM below) ----
    for (int i = tid; i < 2048; i += 256) {
        const int k = i >> 5, rc = i & 31;
        float4 v = ((const float4*)buf)[k * 32 + rc];
        ((float4*)(g_xt + ((size_t)r * CIN + k) * NSEQ + n0))[rc] = v;
    }

    // ---- B: k/v projection GEMM [128 rows x 16 cols x 64 k] ----
    {
        const int rowgrp = tid >> 4;
        const int j      = tid & 15;
        const int rowbase = rowgrp * 8;

        ull acc[4];
#pragma unroll
        for (int rp = 0; rp < 4; rp++) acc[rp] = 0ull;

#pragma unroll 8
        for (int k = 0; k < CIN; k++) {
            ulonglong2 x0 = *(const ulonglong2*)(buf + k * 128 + rowbase);
            ulonglong2 x1 = *(const ulonglong2*)(buf + k * 128 + rowbase + 4);
            ull wd = dup2(wkv_s[k * 16 + j]);
            acc[0] = fma2(x0.x, wd, acc[0]);
            acc[1] = fma2(x0.y, wd, acc[1]);
            acc[2] = fma2(x1.x, wd, acc[2]);
            acc[3] = fma2(x1.y, wd, acc[3]);
        }
#pragma unroll
        for (int rp = 0; rp < 4; rp++) {
            float2 t = unpk(acc[rp]);
            const int row = rowbase + 2 * rp;
            kv_s[row * 16 + j]       = t.x;
            kv_s[(row + 1) * 16 + j] = t.y;
        }
    }

    // ---- q/m partial reduction (register -> warp -> smem) ----
#pragma unroll
    for (int c = 0; c < 16; c++) {
        float v = qacc[c];
        v += __shfl_xor_sync(0xffffffffu, v, 4);
        v += __shfl_xor_sync(0xffffffffu, v, 8);
        v += __shfl_xor_sync(0xffffffffu, v, 16);
        qacc[c] = v;
    }
    {
        float v = wsum(macc);
        if (lane == 0) mred[warp] = v;
    }
    if (lane < 4) {
#pragma unroll
        for (int c = 0; c < 16; c++) qred[warp * 64 + lane * 16 + c] = qacc[c];
    }
    __syncthreads();

    // ---- coalesced kv store ----
    {
        const int n = tid >> 1, half = tid & 1;
        const float4* src = (const float4*)(kv_s + n * 16 + half * 8);
        float4 a = src[0], b = src[1];
        float* dst = (half ? g_v : g_k) + ((size_t)r * NSEQ + n0 + n) * NC;
        ((float4*)dst)[0] = a;
        ((float4*)dst)[1] = b;
    }
    if (tid < CIN) {
        float s2 = 0.f;
#pragma unroll
        for (int w = 0; w < 8; w++) s2 += qred[w * 64 + tid];
        g_qpart[((size_t)r * 16 + by) * CIN + tid] = s2;
    }
    if (tid == 64) {
        float s2 = 0.f;
#pragma unroll
        for (int w = 0; w < 8; w++) s2 += mred[w];
        g_mpart[r * 16 + by] = s2;
    }
}

// =====================================================================
// Pass 2: per column r — q projection, logits, softmax, o accumulation.
// (unchanged)
// =====================================================================
__global__ void __launch_bounds__(512) pass2_kernel(
    const float* __restrict__ mask, const float* __restrict__ wq)
{
    const int r = blockIdx.x;
    const int tid = threadIdx.x;
    const int lane = tid & 31, warp = tid >> 5;
    const int slot = tid >> 1, hp = tid & 1;

    __shared__ float qpre[CIN];
    __shared__ float qh[CIN];
    __shared__ float msum_s;
    __shared__ float redm[16][NH];
    __shared__ float reds[16][NH];
    __shared__ float hmax_s[NH], hsum_s[NH];
    __shared__ float ored[16][CIN];

    if (tid < CIN) {
        float s = 0.f;
#pragma unroll
        for (int p = 0; p < 16; p++) s += g_qpart[((size_t)r * 16 + p) * CIN + tid];
        qpre[tid] = s;
    }
    if (tid == 64) {
        float s = 0.f;
#pragma unroll
        for (int p = 0; p < 16; p++) s += g_mpart[r * 16 + p];
        msum_s = s;
    }
    __syncthreads();
    if (tid < CIN) {
        float a = 0.f;
#pragma unroll
        for (int c = 0; c < CIN; c++) a += qpre[c] * wq[c * CIN + tid];
        qh[tid] = a * 0.3535533905932738f / (msum_s + 1e-10f);
    }
    __syncthreads();

    float l[8][4];
    float hmax[4];
#pragma unroll
    for (int h = 0; h < 4; h++) hmax[h] = -3.4e38f;

#pragma unroll
    for (int i = 0; i < 8; i++) {
        int n = i * 256 + slot;
        const float4* kp = (const float4*)(g_k + ((size_t)r * NSEQ + n) * NC);
        float4 k0 = kp[0], k1 = kp[1];
        float bias = (mask[(size_t)n * NRES + r] - 1.f) * 1000000000.0f;
#pragma unroll
        for (int h = 0; h < 4; h++) {
            const float* q = qh + (hp * 4 + h) * NC;
            float a = q[0] * k0.x + q[1] * k0.y + q[2] * k0.z + q[3] * k0.w
                    + q[4] * k1.x + q[5] * k1.y + q[6] * k1.z + q[7] * k1.w;
            a += bias;
            l[i][h] = a;
            hmax[h] = fmaxf(hmax[h], a);
        }
    }
#pragma unroll
    for (int h = 0; h < 4; h++) {
        float v = hmax[h];
#pragma unroll
        for (int o = 16; o >= 2; o >>= 1) v = fmaxf(v, __shfl_xor_sync(0xffffffffu, v, o));
        hmax[h] = v;
    }
    if (lane < 2) {
#pragma unroll
        for (int h = 0; h < 4; h++) redm[warp][lane * 4 + h] = hmax[h];
    }
    __syncthreads();
    if (tid < NH) {
        float v = -3.4e38f;
#pragma unroll
        for (int w = 0; w < 16; w++) v = fmaxf(v, redm[w][tid]);
        hmax_s[tid] = v;
    }
    __syncthreads();

    float hsum[4];
#pragma unroll
    for (int h = 0; h < 4; h++) hsum[h] = 0.f;
    float oacc[32];
#pragma unroll
    for (int j = 0; j < 32; j++) oacc[j] = 0.f;

#pragma unroll
    for (int i = 0; i < 8; i++) {
        int n = i * 256 + slot;
        const float4* vp = (const float4*)(g_v + ((size_t)r * NSEQ + n) * NC);
        float4 v0 = vp[0], v1 = vp[1];
#pragma unroll
        for (int h = 0; h < 4; h++) {
            float p = __expf(l[i][h] - hmax_s[hp * 4 + h]);
            hsum[h] += p;
            oacc[h * 8 + 0] += p * v0.x; oacc[h * 8 + 1] += p * v0.y;
            oacc[h * 8 + 2] += p * v0.z; oacc[h * 8 + 3] += p * v0.w;
            oacc[h * 8 + 4] += p * v1.x; oacc[h * 8 + 5] += p * v1.y;
            oacc[h * 8 + 6] += p * v1.z; oacc[h * 8 + 7] += p * v1.w;
        }
    }
#pragma unroll
    for (int h = 0; h < 4; h++) {
        float v = hsum[h];
#pragma unroll
        for (int o = 16; o >= 2; o >>= 1) v += __shfl_xor_sync(0xffffffffu, v, o);
        hsum[h] = v;
    }
#pragma unroll
    for (int j = 0; j < 32; j++) {
        float v = oacc[j];
#pragma unroll
        for (int o = 16; o >= 2; o >>= 1) v += __shfl_xor_sync(0xffffffffu, v, o);
        oacc[j] = v;
    }
    if (lane < 2) {
#pragma unroll
        for (int h = 0; h < 4; h++) reds[warp][lane * 4 + h] = hsum[h];
#pragma unroll
        for (int j = 0; j < 32; j++) ored[warp][lane * 32 + j] = oacc[j];
    }
    __syncthreads();
    if (tid < NH) {
        float v = 0.f;
#pragma unroll
        for (int w = 0; w < 16; w++) v += reds[w][tid];
        hsum_s[tid] = v;
    }
    __syncthreads();
    if (tid < CIN) {
        float s2 = 0.f;
#pragma unroll
        for (int w = 0; w < 16; w++) s2 += ored[w][tid];
        g_o[r * CIN + tid] = s2 / hsum_s[tid >> 3];
    }
}

// =====================================================================
// Pass 3 v6 (hot): block = (r, 128 n-rows), 3 CTAs/SM (66 KB smem).
// Reads pre-normalized X^T from g_xt. Thread tile 8 rows x 4 cols.
// Y stored with ((col>>2)&7)<<2 row-XOR swizzle.
// =====================================================================
#define P3_SMEM_FLOATS (8192 /*buf*/ + 4096 /*wg*/ + 4096 /*wo*/ + 192)
#define P3_SMEM_BYTES  (P3_SMEM_FLOATS * 4)

__global__ void __launch_bounds__(256, 3) pass3_kernel(
    const float* __restrict__ wg, const float* __restrict__ bg,
    const float* __restrict__ wo, const float* __restrict__ bo,
    float* __restrict__ out)
{
    extern __shared__ __align__(16) float sm3[];
    float* buf  = sm3;                 // 8192: X[k][128] -> Y (swizzled)
    float* wg_s = sm3 + 8192;          // 4096
    float* wo_s = sm3 + 12288;         // 4096
    float* o_s  = sm3 + 16384;
    float* bg_s = o_s + 64;
    float* bo_s = bg_s + 64;

    const int r   = blockIdx.x;
    const int tid = threadIdx.x;
    const int n0  = blockIdx.y * 128;

    for (int i = tid; i < CIN * CIN; i += 256) { wg_s[i] = wg[i]; wo_s[i] = wo[i]; }
    if (tid < CIN) {
        o_s[tid]  = g_o[r * CIN + tid];
        bg_s[tid] = bg[tid]; bo_s[tid] = bo[tid];
    }

    // ---- Stage A: coalesced X^T tile copy ----
#pragma unroll
    for (int t = 0; t < 8; t++) {
        const int i = t * 256 + tid;
        const int k = i >> 5, rc = i & 31;
        float4 v = ((const float4*)(g_xt + ((size_t)r * CIN + k) * NSEQ + n0))[rc];
        ((float4*)buf)[k * 32 + rc] = v;
    }
    __syncthreads();

    const int rowgrp = tid >> 4;          // 0..15
    const int colgrp = tid & 15;          // 0..15
    const int rowbase = rowgrp * 8;
    const int colbase = colgrp * 4;
    const int sc = (colgrp & 7) << 2;     // Y swizzle for this thread's cols

    ull acc[4][4];

    // ================= GEMM 1: gpre = X @ Wg =================
#pragma unroll
    for (int rp = 0; rp < 4; rp++)
#pragma unroll
        for (int c = 0; c < 4; c++) acc[rp][c] = 0ull;

#pragma unroll 4
    for (int k = 0; k < CIN; k++) {
        ulonglong2 x0 = *(const ulonglong2*)(buf + k * 128 + rowbase);
        ulonglong2 x1 = *(const ulonglong2*)(buf + k * 128 + rowbase + 4);
        float4 w = *(const float4*)(wg_s + k * CIN + colbase);
        ull wd0 = dup2(w.x), wd1 = dup2(w.y), wd2 = dup2(w.z), wd3 = dup2(w.w);
        ull xs[4] = {x0.x, x0.y, x1.x, x1.y};
#pragma unroll
        for (int rp = 0; rp < 4; rp++) {
            acc[rp][0] = fma2(xs[rp], wd0, acc[rp][0]);
            acc[rp][1] = fma2(xs[rp], wd1, acc[rp][1]);
            acc[rp][2] = fma2(xs[rp], wd2, acc[rp][2]);
            acc[rp][3] = fma2(xs[rp], wd3, acc[rp][3]);
        }
    }
    __syncthreads();   // all X reads done before Y overwrites buf

    // ---- epilogue 1: y = o * sigmoid(gpre + bg) -> buf[col][row ^ sc] ----
#pragma unroll
    for (int c = 0; c < 4; c++) {
        const int col = colbase + c;
        const float bgc = bg_s[col];
        const float oc  = o_s[col];
#pragma unroll
        for (int rp = 0; rp < 4; rp++) {
            float2 t = unpk(acc[rp][c]);
            float y0 = oc / (1.f + __expf(-(t.x + bgc)));
            float y1 = oc / (1.f + __expf(-(t.y + bgc)));
            const int row = rowbase + 2 * rp;
            *(ull*)(buf + col * 128 + (row ^ sc)) = pack2(y0, y1);
        }
    }
    __syncthreads();

    // ================= GEMM 2: out = Y @ Wo =================
#pragma unroll
    for (int rp = 0; rp < 4; rp++)
#pragma unroll
        for (int c = 0; c < 4; c++) acc[rp][c] = 0ull;

#pragma unroll 4
    for (int k = 0; k < CIN; k++) {
        const int sck = ((k >> 2) & 7) << 2;
        ulonglong2 x0 = *(const ulonglong2*)(buf + k * 128 + (rowbase ^ sck));
        ulonglong2 x1 = *(const ulonglong2*)(buf + k * 128 + ((rowbase + 4) ^ sck));
        float4 w = *(const float4*)(wo_s + k * CIN + colbase);
        ull wd0 = dup2(w.x), wd1 = dup2(w.y), wd2 = dup2(w.z), wd3 = dup2(w.w);
        ull xs[4] = {x0.x, x0.y, x1.x, x1.y};
#pragma unroll
        for (int rp = 0; rp < 4; rp++) {
            acc[rp][0] = fma2(xs[rp], wd0, acc[rp][0]);
            acc[rp][1] = fma2(xs[rp], wd1, acc[rp][1]);
            acc[rp][2] = fma2(xs[rp], wd2, acc[rp][2]);
            acc[rp][3] = fma2(xs[rp], wd3, acc[rp][3]);
        }
    }

    // ---- epilogue 2: add bias, store directly to global ----
    {
        const float b0 = bo_s[colbase + 0], b1 = bo_s[colbase + 1];
        const float b2 = bo_s[colbase + 2], b3 = bo_s[colbase + 3];
#pragma unroll
        for (int rp = 0; rp < 4; rp++) {
            float2 t0 = unpk(acc[rp][0]), t1 = unpk(acc[rp][1]);
            float2 t2 = unpk(acc[rp][2]), t3 = unpk(acc[rp][3]);
            const int row = rowbase + 2 * rp;
            float4 v;
            v.x = t0.x + b0; v.y = t1.x + b1; v.z = t2.x + b2; v.w = t3.x + b3;
            *(float4*)(out + ((size_t)(n0 + row) * NRES + r) * CIN + colbase) = v;
            v.x = t0.y + b0; v.y = t1.y + b1; v.z = t2.y + b2; v.w = t3.y + b3;
            *(float4*)(out + ((size_t)(n0 + row + 1) * NRES + r) * CIN + colbase) = v;
        }
    }
}

extern "C" void kernel_launch(void* const* d_in, const int* in_sizes, int n_in,
                              void* d_out, int out_size) {
    const float* m    = (const float*)d_in[0];
    const float* mask = (const float*)d_in[1];
    const float* lnw  = (const float*)d_in[2];
    const float* lnb  = (const float*)d_in[3];
    const float* wq   = (const float*)d_in[4];
    const float* wk   = (const float*)d_in[5];
    const float* wv   = (const float*)d_in[6];
    const float* wg   = (const float*)d_in[7];
    const float* bg   = (const float*)d_in[8];
    const float* wo   = (const float*)d_in[9];
    const float* bo   = (const float*)d_in[10];
    float* out = (float*)d_out;

    cudaFuncSetAttribute(pass1_kernel,
                         cudaFuncAttributeMaxDynamicSharedMemorySize, P1_SMEM_BYTES);
    cudaFuncSetAttribute(pass3_kernel,
                         cudaFuncAttributeMaxDynamicSharedMemorySize, P3_SMEM_BYTES);

    pass1_kernel<<<dim3(NRES, 16), 256, P1_SMEM_BYTES>>>(m, mask, lnw, lnb, wk, wv);
    pass2_kernel<<<NRES, 512>>>(mask, wq);
    pass3_kernel<<<dim3(NRES, 16), 256, P3_SMEM_BYTES>>>(wg, bg, wo, bo, out);
}

// round 9
// speedup vs baseline: 2.6200x; 1.0379x over previous
#include <cuda_runtime.h>

typedef unsigned long long ull;

#define NSEQ 2048
#define NRES 512
#define CIN  64
#define NH   8
#define NC   8

// ---------------- scratch (device globals: allocation-free) ----------------
__device__ __align__(16) float g_k[(size_t)NRES * NSEQ * NC];      // 32 MB
__device__ __align__(16) float g_v[(size_t)NRES * NSEQ * NC];      // 32 MB
__device__ __align__(16) float g_xt[(size_t)NRES * CIN * NSEQ];    // 256 MB  X^T [r][k][n]
__device__ __align__(16) float g_qpart[NRES * 16 * CIN];
__device__ __align__(16) float g_mpart[NRES * 16];
__device__ __align__(16) float g_o[NRES * CIN];

// ---------------- packed f32x2 helpers ----------------
__device__ __forceinline__ ull fma2(ull a, ull b, ull c) {
    ull d;
    asm("fma.rn.f32x2 %0, %1, %2, %3;" : "=l"(d) : "l"(a), "l"(b), "l"(c));
    return d;
}
__device__ __forceinline__ ull dup2(float x) {
    ull d; unsigned xi = __float_as_uint(x);
    asm("mov.b64 %0, {%1, %1};" : "=l"(d) : "r"(xi));
    return d;
}
__device__ __forceinline__ ull pack2(float lo, float hi) {
    ull d;
    asm("mov.b64 %0, {%1, %2};" : "=l"(d) : "r"(__float_as_uint(lo)), "r"(__float_as_uint(hi)));
    return d;
}
__device__ __forceinline__ float2 unpk(ull a) {
    unsigned lo, hi;
    asm("mov.b64 {%0, %1}, %2;" : "=r"(lo), "=r"(hi) : "l"(a));
    return make_float2(__uint_as_float(lo), __uint_as_float(hi));
}
__device__ __forceinline__ float wsum(float v) {
#pragma unroll
    for (int o = 16; o; o >>= 1) v += __shfl_xor_sync(0xffffffffu, v, o);
    return v;
}

// =====================================================================
// Pass 1 v5: block = (r, 128 n-rows), 4 CTAs/SM (57 KB smem, <=64 regs).
// LN stats computed from raw, then raw re-read to normalize (keeps
// register peak ~35). q/m reduction done before the kv GEMM.
// kv weights stored transposed [j][68] and read as LDS.128.
// =====================================================================
#define P1_SMEM_FLOATS (8192 /*buf*/ + 4352 /*raw|kv_s*/ + 1088 /*wkv_t*/ + 128 /*ln*/ + 512 /*qred*/ + 8 /*mred*/)
#define P1_SMEM_BYTES  (P1_SMEM_FLOATS * 4)

__global__ void __launch_bounds__(256, 4) pass1_kernel(
    const float* __restrict__ m, const float* __restrict__ mask,
    const float* __restrict__ lnw, const float* __restrict__ lnb,
    const float* __restrict__ wk, const float* __restrict__ wv)
{
    extern __shared__ __align__(16) float sm1[];
    float* buf    = sm1;                    // 8192: X[k][128]
    float* raw    = sm1 + 8192;             // 4352: m half-tile [row][68] (aliased by kv_s)
    float* kv_s   = sm1 + 8192;             // 2048: kv staging (after raw dead)
    float* wkv_t  = sm1 + 12544;            // 1088: w^T [j][68]
    float* lnw_s  = sm1 + 13632;            // 64
    float* lnb_s  = sm1 + 13696;            // 64
    float* qred   = sm1 + 13760;            // 8 warps x 64
    float* mred   = sm1 + 14272;            // 8

    const int r   = blockIdx.x;
    const int by  = blockIdx.y;
    const int n0  = by * 128;
    const int tid = threadIdx.x;
    const int lane = tid & 31, warp = tid >> 5;
    const int slot = tid >> 2, quarter = tid & 3;   // LN: 4 threads/row
    const int cb   = quarter * 16;

    // wkv transposed: wkv_t[j][k], j<8 -> wk col j, j>=8 -> wv col j-8
    for (int i = tid; i < 16 * CIN; i += 256) {
        int j = i >> 6, k = i & 63;
        wkv_t[j * 68 + k] = (j < 8) ? wk[k * 8 + j] : wv[k * 8 + (j - 8)];
    }
    if (tid < CIN) { lnw_s[tid] = lnw[tid]; lnb_s[tid] = lnb[tid]; }
    __syncthreads();

    float qacc[16];
#pragma unroll
    for (int c = 0; c < 16; c++) qacc[c] = 0.f;
    float macc = 0.f;

#pragma unroll
    for (int half = 0; half < 2; half++) {
        // ---- A0: coalesced 64-row m half-tile -> raw ----
        for (int i = tid; i < 1024; i += 256) {
            const int row = i >> 4, k4 = i & 15;
            float4 v = *(const float4*)(m + ((size_t)(n0 + half * 64 + row) * NRES + r) * CIN + k4 * 4);
            *(float4*)(raw + row * 68 + k4 * 4) = v;
        }
        __syncthreads();

        // ---- A1: LN stats from raw, then re-read raw to normalize ----
        {
            const float4* rr = (const float4*)(raw + slot * 68 + cb);
            float s = 0.f, sq = 0.f;
#pragma unroll
            for (int k = 0; k < 4; k++) {
                float4 v4 = rr[k];
                s  += v4.x + v4.y + v4.z + v4.w;
                sq += v4.x * v4.x + v4.y * v4.y + v4.z * v4.z + v4.w * v4.w;
            }
            s  += __shfl_xor_sync(0xffffffffu, s, 1);
            sq += __shfl_xor_sync(0xffffffffu, sq, 1);
            s  += __shfl_xor_sync(0xffffffffu, s, 2);
            sq += __shfl_xor_sync(0xffffffffu, sq, 2);
            float mu = s * (1.f / CIN);
            float rs = rsqrtf(sq * (1.f / CIN) - mu * mu + 1e-5f);
            const int row_g = half * 64 + slot;
            const float mv = mask[(size_t)(n0 + row_g) * NRES + r];
#pragma unroll
            for (int k = 0; k < 4; k++) {
                float4 v4 = rr[k];
                float x0 = (v4.x - mu) * rs * lnw_s[cb + 4 * k + 0] + lnb_s[cb + 4 * k + 0];
                float x1 = (v4.y - mu) * rs * lnw_s[cb + 4 * k + 1] + lnb_s[cb + 4 * k + 1];
                float x2 = (v4.z - mu) * rs * lnw_s[cb + 4 * k + 2] + lnb_s[cb + 4 * k + 2];
                float x3 = (v4.w - mu) * rs * lnw_s[cb + 4 * k + 3] + lnb_s[cb + 4 * k + 3];
                buf[(cb + 4 * k + 0) * 128 + row_g] = x0;
                buf[(cb + 4 * k + 1) * 128 + row_g] = x1;
                buf[(cb + 4 * k + 2) * 128 + row_g] = x2;
                buf[(cb + 4 * k + 3) * 128 + row_g] = x3;
                qacc[4 * k + 0] += mv * x0;
                qacc[4 * k + 1] += mv * x1;
                qacc[4 * k + 2] += mv * x2;
                qacc[4 * k + 3] += mv * x3;
            }
            if (quarter == 0) macc += mv;
        }
        __syncthreads();
    }

    // ---- q/m partial reduction (frees qacc before the GEMM) ----
#pragma unroll
    for (int c = 0; c < 16; c++) {
        float v = qacc[c];
        v += __shfl_xor_sync(0xffffffffu, v, 4);
        v += __shfl_xor_sync(0xffffffffu, v, 8);
        v += __shfl_xor_sync(0xffffffffu, v, 16);
        qacc[c] = v;
    }
    {
        float v = wsum(macc);
        if (lane == 0) mred[warp] = v;
    }
    if (lane < 4) {
#pragma unroll
        for (int c = 0; c < 16; c++) qred[warp * 64 + lane * 16 + c] = qacc[c];
    }

    // ---- X^T store (latency overlaps with the kv GEMM below) ----
    for (int i = tid; i < 2048; i += 256) {
        const int k = i >> 5, rc = i & 31;
        float4 v = ((const float4*)buf)[k * 32 + rc];
        ((float4*)(g_xt + ((size_t)r * CIN + k) * NSEQ + n0))[rc] = v;
    }

    // ---- B: k/v projection GEMM [128 rows x 16 cols x 64 k] ----
    {
        const int rowgrp = tid >> 4;
        const int j      = tid & 15;
        const int rowbase = rowgrp * 8;

        ull acc[4];
#pragma unroll
        for (int rp = 0; rp < 4; rp++) acc[rp] = 0ull;

#pragma unroll 4
        for (int k4 = 0; k4 < CIN; k4 += 4) {
            float4 w4 = *(const float4*)(wkv_t + j * 68 + k4);
#pragma unroll
            for (int kk = 0; kk < 4; kk++) {
                const int k = k4 + kk;
                ulonglong2 x0 = *(const ulonglong2*)(buf + k * 128 + rowbase);
                ulonglong2 x1 = *(const ulonglong2*)(buf + k * 128 + rowbase + 4);
                ull wd = dup2(kk == 0 ? w4.x : kk == 1 ? w4.y : kk == 2 ? w4.z : w4.w);
                acc[0] = fma2(x0.x, wd, acc[0]);
                acc[1] = fma2(x0.y, wd, acc[1]);
                acc[2] = fma2(x1.x, wd, acc[2]);
                acc[3] = fma2(x1.y, wd, acc[3]);
            }
        }
#pragma unroll
        for (int rp = 0; rp < 4; rp++) {
            float2 t = unpk(acc[rp]);
            const int row = rowbase + 2 * rp;
            kv_s[row * 16 + j]       = t.x;
            kv_s[(row + 1) * 16 + j] = t.y;
        }
    }
    __syncthreads();

    // ---- coalesced kv store + q/m partials to global ----
    {
        const int n = tid >> 1, half = tid & 1;
        const float4* src = (const float4*)(kv_s + n * 16 + half * 8);
        float4 a = src[0], b = src[1];
        float* dst = (half ? g_v : g_k) + ((size_t)r * NSEQ + n0 + n) * NC;
        ((float4*)dst)[0] = a;
        ((float4*)dst)[1] = b;
    }
    if (tid < CIN) {
        float s2 = 0.f;
#pragma unroll
        for (int w = 0; w < 8; w++) s2 += qred[w * 64 + tid];
        g_qpart[((size_t)r * 16 + by) * CIN + tid] = s2;
    }
    if (tid == 64) {
        float s2 = 0.f;
#pragma unroll
        for (int w = 0; w < 8; w++) s2 += mred[w];
        g_mpart[r * 16 + by] = s2;
    }
}

// =====================================================================
// Pass 2: per column r — q projection, logits, softmax, o accumulation.
// (unchanged)
// =====================================================================
__global__ void __launch_bounds__(512) pass2_kernel(
    const float* __restrict__ mask, const float* __restrict__ wq)
{
    const int r = blockIdx.x;
    const int tid = threadIdx.x;
    const int lane = tid & 31, warp = tid >> 5;
    const int slot = tid >> 1, hp = tid & 1;

    __shared__ float qpre[CIN];
    __shared__ float qh[CIN];
    __shared__ float msum_s;
    __shared__ float redm[16][NH];
    __shared__ float reds[16][NH];
    __shared__ float hmax_s[NH], hsum_s[NH];
    __shared__ float ored[16][CIN];

    if (tid < CIN) {
        float s = 0.f;
#pragma unroll
        for (int p = 0; p < 16; p++) s += g_qpart[((size_t)r * 16 + p) * CIN + tid];
        qpre[tid] = s;
    }
    if (tid == 64) {
        float s = 0.f;
#pragma unroll
        for (int p = 0; p < 16; p++) s += g_mpart[r * 16 + p];
        msum_s = s;
    }
    __syncthreads();
    if (tid < CIN) {
        float a = 0.f;
#pragma unroll
        for (int c = 0; c < CIN; c++) a += qpre[c] * wq[c * CIN + tid];
        qh[tid] = a * 0.3535533905932738f / (msum_s + 1e-10f);
    }
    __syncthreads();

    float l[8][4];
    float hmax[4];
#pragma unroll
    for (int h = 0; h < 4; h++) hmax[h] = -3.4e38f;

#pragma unroll
    for (int i = 0; i < 8; i++) {
        int n = i * 256 + slot;
        const float4* kp = (const float4*)(g_k + ((size_t)r * NSEQ + n) * NC);
        float4 k0 = kp[0], k1 = kp[1];
        float bias = (mask[(size_t)n * NRES + r] - 1.f) * 1000000000.0f;
#pragma unroll
        for (int h = 0; h < 4; h++) {
            const float* q = qh + (hp * 4 + h) * NC;
            float a = q[0] * k0.x + q[1] * k0.y + q[2] * k0.z + q[3] * k0.w
                    + q[4] * k1.x + q[5] * k1.y + q[6] * k1.z + q[7] * k1.w;
            a += bias;
            l[i][h] = a;
            hmax[h] = fmaxf(hmax[h], a);
        }
    }
#pragma unroll
    for (int h = 0; h < 4; h++) {
        float v = hmax[h];
#pragma unroll
        for (int o = 16; o >= 2; o >>= 1) v = fmaxf(v, __shfl_xor_sync(0xffffffffu, v, o));
        hmax[h] = v;
    }
    if (lane < 2) {
#pragma unroll
        for (int h = 0; h < 4; h++) redm[warp][lane * 4 + h] = hmax[h];
    }
    __syncthreads();
    if (tid < NH) {
        float v = -3.4e38f;
#pragma unroll
        for (int w = 0; w < 16; w++) v = fmaxf(v, redm[w][tid]);
        hmax_s[tid] = v;
    }
    __syncthreads();

    float hsum[4];
#pragma unroll
    for (int h = 0; h < 4; h++) hsum[h] = 0.f;
    float oacc[32];
#pragma unroll
    for (int j = 0; j < 32; j++) oacc[j] = 0.f;

#pragma unroll
    for (int i = 0; i < 8; i++) {
        int n = i * 256 + slot;
        const float4* vp = (const float4*)(g_v + ((size_t)r * NSEQ + n) * NC);
        float4 v0 = vp[0], v1 = vp[1];
#pragma unroll
        for (int h = 0; h < 4; h++) {
            float p = __expf(l[i][h] - hmax_s[hp * 4 + h]);
            hsum[h] += p;
            oacc[h * 8 + 0] += p * v0.x; oacc[h * 8 + 1] += p * v0.y;
            oacc[h * 8 + 2] += p * v0.z; oacc[h * 8 + 3] += p * v0.w;
            oacc[h * 8 + 4] += p * v1.x; oacc[h * 8 + 5] += p * v1.y;
            oacc[h * 8 + 6] += p * v1.z; oacc[h * 8 + 7] += p * v1.w;
        }
    }
#pragma unroll
    for (int h = 0; h < 4; h++) {
        float v = hsum[h];
#pragma unroll
        for (int o = 16; o >= 2; o >>= 1) v += __shfl_xor_sync(0xffffffffu, v, o);
        hsum[h] = v;
    }
#pragma unroll
    for (int j = 0; j < 32; j++) {
        float v = oacc[j];
#pragma unroll
        for (int o = 16; o >= 2; o >>= 1) v += __shfl_xor_sync(0xffffffffu, v, o);
        oacc[j] = v;
    }
    if (lane < 2) {
#pragma unroll
        for (int h = 0; h < 4; h++) reds[warp][lane * 4 + h] = hsum[h];
#pragma unroll
        for (int j = 0; j < 32; j++) ored[warp][lane * 32 + j] = oacc[j];
    }
    __syncthreads();
    if (tid < NH) {
        float v = 0.f;
#pragma unroll
        for (int w = 0; w < 16; w++) v += reds[w][tid];
        hsum_s[tid] = v;
    }
    __syncthreads();
    if (tid < CIN) {
        float s2 = 0.f;
#pragma unroll
        for (int w = 0; w < 16; w++) s2 += ored[w][tid];
        g_o[r * CIN + tid] = s2 / hsum_s[tid >> 3];
    }
}

// =====================================================================
// Pass 3 v7 (hot): block = (r, 128 n-rows), 3 CTAs/SM (66 KB smem).
// Reads pre-normalized X^T from g_xt. Thread tile 8 rows x 4 cols.
// Y stored with ((col>>2)&7)<<2 row-XOR swizzle. k-loops unrolled x8.
// =====================================================================
#define P3_SMEM_FLOATS (8192 /*buf*/ + 4096 /*wg*/ + 4096 /*wo*/ + 192)
#define P3_SMEM_BYTES  (P3_SMEM_FLOATS * 4)

__global__ void __launch_bounds__(256, 3) pass3_kernel(
    const float* __restrict__ wg, const float* __restrict__ bg,
    const float* __restrict__ wo, const float* __restrict__ bo,
    float* __restrict__ out)
{
    extern __shared__ __align__(16) float sm3[];
    float* buf  = sm3;                 // 8192: X[k][128] -> Y (swizzled)
    float* wg_s = sm3 + 8192;          // 4096
    float* wo_s = sm3 + 12288;         // 4096
    float* o_s  = sm3 + 16384;
    float* bg_s = o_s + 64;
    float* bo_s = bg_s + 64;

    const int r   = blockIdx.x;
    const int tid = threadIdx.x;
    const int n0  = blockIdx.y * 128;

    for (int i = tid; i < CIN * CIN; i += 256) { wg_s[i] = wg[i]; wo_s[i] = wo[i]; }
    if (tid < CIN) {
        o_s[tid]  = g_o[r * CIN + tid];
        bg_s[tid] = bg[tid]; bo_s[tid] = bo[tid];
    }

    // ---- Stage A: coalesced X^T tile copy ----
#pragma unroll
    for (int t = 0; t < 8; t++) {
        const int i = t * 256 + tid;
        const int k = i >> 5, rc = i & 31;
        float4 v = ((const float4*)(g_xt + ((size_t)r * CIN + k) * NSEQ + n0))[rc];
        ((float4*)buf)[k * 32 + rc] = v;
    }
    __syncthreads();

    const int rowgrp = tid >> 4;          // 0..15
    const int colgrp = tid & 15;          // 0..15
    const int rowbase = rowgrp * 8;
    const int colbase = colgrp * 4;
    const int sc = (colgrp & 7) << 2;     // Y swizzle for this thread's cols

    ull acc[4][4];

    // ================= GEMM 1: gpre = X @ Wg =================
#pragma unroll
    for (int rp = 0; rp < 4; rp++)
#pragma unroll
        for (int c = 0; c < 4; c++) acc[rp][c] = 0ull;

#pragma unroll 8
    for (int k = 0; k < CIN; k++) {
        ulonglong2 x0 = *(const ulonglong2*)(buf + k * 128 + rowbase);
        ulonglong2 x1 = *(const ulonglong2*)(buf + k * 128 + rowbase + 4);
        float4 w = *(const float4*)(wg_s + k * CIN + colbase);
        ull wd0 = dup2(w.x), wd1 = dup2(w.y), wd2 = dup2(w.z), wd3 = dup2(w.w);
        ull xs[4] = {x0.x, x0.y, x1.x, x1.y};
#pragma unroll
        for (int rp = 0; rp < 4; rp++) {
            acc[rp][0] = fma2(xs[rp], wd0, acc[rp][0]);
            acc[rp][1] = fma2(xs[rp], wd1, acc[rp][1]);
            acc[rp][2] = fma2(xs[rp], wd2, acc[rp][2]);
            acc[rp][3] = fma2(xs[rp], wd3, acc[rp][3]);
        }
    }
    __syncthreads();   // all X reads done before Y overwrites buf

    // ---- epilogue 1: y = o * sigmoid(gpre + bg) -> buf[col][row ^ sc] ----
#pragma unroll
    for (int c = 0; c < 4; c++) {
        const int col = colbase + c;
        const float bgc = bg_s[col];
        const float oc  = o_s[col];
#pragma unroll
        for (int rp = 0; rp < 4; rp++) {
            float2 t = unpk(acc[rp][c]);
            float y0 = oc / (1.f + __expf(-(t.x + bgc)));
            float y1 = oc / (1.f + __expf(-(t.y + bgc)));
            const int row = rowbase + 2 * rp;
            *(ull*)(buf + col * 128 + (row ^ sc)) = pack2(y0, y1);
        }
    }
    __syncthreads();

    // ================= GEMM 2: out = Y @ Wo =================
#pragma unroll
    for (int rp = 0; rp < 4; rp++)
#pragma unroll
        for (int c = 0; c < 4; c++) acc[rp][c] = 0ull;

#pragma unroll 8
    for (int k = 0; k < CIN; k++) {
        const int sck = ((k >> 2) & 7) << 2;
        ulonglong2 x0 = *(const ulonglong2*)(buf + k * 128 + (rowbase ^ sck));
        ulonglong2 x1 = *(const ulonglong2*)(buf + k * 128 + ((rowbase + 4) ^ sck));
        float4 w = *(const float4*)(wo_s + k * CIN + colbase);
        ull wd0 = dup2(w.x), wd1 = dup2(w.y), wd2 = dup2(w.z), wd3 = dup2(w.w);
        ull xs[4] = {x0.x, x0.y, x1.x, x1.y};
#pragma unroll
        for (int rp = 0; rp < 4; rp++) {
            acc[rp][0] = fma2(xs[rp], wd0, acc[rp][0]);
            acc[rp][1] = fma2(xs[rp], wd1, acc[rp][1]);
            acc[rp][2] = fma2(xs[rp], wd2, acc[rp][2]);
            acc[rp][3] = fma2(xs[rp], wd3, acc[rp][3]);
        }
    }

    // ---- epilogue 2: add bias, store directly to global ----
    {
        const float b0 = bo_s[colbase + 0], b1 = bo_s[colbase + 1];
        const float b2 = bo_s[colbase + 2], b3 = bo_s[colbase + 3];
#pragma unroll
        for (int rp = 0; rp < 4; rp++) {
            float2 t0 = unpk(acc[rp][0]), t1 = unpk(acc[rp][1]);
            float2 t2 = unpk(acc[rp][2]), t3 = unpk(acc[rp][3]);
            const int row = rowbase + 2 * rp;
            float4 v;
            v.x = t0.x + b0; v.y = t1.x + b1; v.z = t2.x + b2; v.w = t3.x + b3;
            *(float4*)(out + ((size_t)(n0 + row) * NRES + r) * CIN + colbase) = v;
            v.x = t0.y + b0; v.y = t1.y + b1; v.z = t2.y + b2; v.w = t3.y + b3;
            *(float4*)(out + ((size_t)(n0 + row + 1) * NRES + r) * CIN + colbase) = v;
        }
    }
}

extern "C" void kernel_launch(void* const* d_in, const int* in_sizes, int n_in,
                              void* d_out, int out_size) {
    const float* m    = (const float*)d_in[0];
    const float* mask = (const float*)d_in[1];
    const float* lnw  = (const float*)d_in[2];
    const float* lnb  = (const float*)d_in[3];
    const float* wq   = (const float*)d_in[4];
    const float* wk   = (const float*)d_in[5];
    const float* wv   = (const float*)d_in[6];
    const float* wg   = (const float*)d_in[7];
    const float* bg   = (const float*)d_in[8];
    const float* wo   = (const float*)d_in[9];
    const float* bo   = (const float*)d_in[10];
    float* out = (float*)d_out;

    cudaFuncSetAttribute(pass1_kernel,
                         cudaFuncAttributeMaxDynamicSharedMemorySize, P1_SMEM_BYTES);
    cudaFuncSetAttribute(pass3_kernel,
                         cudaFuncAttributeMaxDynamicSharedMemorySize, P3_SMEM_BYTES);

    pass1_kernel<<<dim3(NRES, 16), 256, P1_SMEM_BYTES>>>(m, mask, lnw, lnb, wk, wv);
    pass2_kernel<<<NRES, 512>>>(mask, wq);
    pass3_kernel<<<dim3(NRES, 16), 256, P3_SMEM_BYTES>>>(wg, bg, wo, bo, out);
}